// round 10
// baseline (speedup 1.0000x reference)
#include <cuda_runtime.h>
#include <cuda_bf16.h>
#include <cstdint>

#define NN   50000
#define DEG  16
#define FD   160
#define HD   160
#define GD   640
#define OC   128
#define KHH  160

// prep (fp32) config — proven machinery
#define PTM  64
#define PNT  512
#define PKC  16
#define PNCH (KHH/PKC)
#define PCHF (PKC*GD)
#define PCHB (PCHF*4)

// main MMA kernel config
#define TM   64
#define NT   256
#define HPLANE 21504               // bytes per h plane (64*168*2)
#define HBUFB  43008               // bytes per h buffer (2 planes)
#define SM_B   86016               // B double buffer: 2 x 25600
#define SM_CST 137216              // 40*256*4
#define SM_SRC 178176              // 2*64 ints
#define SM_MAIN 178688

typedef unsigned long long ull;

// ---------------- device scratch ----------------
__device__ float g_hin[NN * FD];
__device__ float g_WihP[KHH * HD * 4];   // [k][m][4]
__device__ float g_bias[GD];             // [m][4]
__device__ float g_WlP[KHH * OC];
__device__ float g_WrP[KHH * OC];
__device__ float g_P[NN * GD];           // [node][4m+g], biases folded
__device__ float g_Q[NN * OC];
// Whh bf16 split: [pl 2][q 4][kc 10][n 160][16]
__device__ __align__(16) __nv_bfloat16 g_Wb[2 * 4 * 10 * 160 * 16];

// ---------------- helpers ----------------
__device__ __forceinline__ ull pack2(float lo, float hi) {
    ull v; asm("mov.b64 %0, {%1, %2};" : "=l"(v) : "f"(lo), "f"(hi)); return v;
}
__device__ __forceinline__ void unpack2(ull v, float& lo, float& hi) {
    asm("mov.b64 {%0, %1}, %2;" : "=f"(lo), "=f"(hi) : "l"(v));
}
__device__ __forceinline__ void fma2(ull& d, ull a, ull b) {
    asm("fma.rn.f32x2 %0, %1, %2, %0;" : "+l"(d) : "l"(a), "l"(b));
}
__device__ __forceinline__ void ldsv2(uint32_t a, ull& x, ull& y) {
    asm("ld.shared.v2.u64 {%0,%1}, [%2];" : "=l"(x), "=l"(y) : "r"(a));
}
__device__ __forceinline__ uint32_t lds32(uint32_t a) {
    uint32_t v; asm("ld.shared.b32 %0, [%1];" : "=r"(v) : "r"(a)); return v;
}
__device__ __forceinline__ void cp16(uint32_t s, const void* g) {
    asm volatile("cp.async.ca.shared.global [%0], [%1], 16;" :: "r"(s), "l"(g));
}
__device__ __forceinline__ void cpcommit() { asm volatile("cp.async.commit_group;"); }
template<int N> __device__ __forceinline__ void cpwait() {
    asm volatile("cp.async.wait_group %0;" :: "n"(N));
}
__device__ __forceinline__ float sigm(float x) { return __fdividef(1.f, 1.f + __expf(-x)); }
__device__ __forceinline__ float tanhfast(float x) {
    return __fdividef(2.f, 1.f + __expf(-2.f * x)) - 1.f;
}
__device__ __forceinline__ void mma_bf16(float* d, const uint32_t* a, uint32_t b0, uint32_t b1) {
    asm volatile("mma.sync.aligned.m16n8k16.row.col.f32.bf16.bf16.f32 "
                 "{%0,%1,%2,%3}, {%4,%5,%6,%7}, {%8,%9}, {%0,%1,%2,%3};"
                 : "+f"(d[0]), "+f"(d[1]), "+f"(d[2]), "+f"(d[3])
                 : "r"(a[0]), "r"(a[1]), "r"(a[2]), "r"(a[3]), "r"(b0), "r"(b1));
}

// ---------------- prep kernels ----------------
__global__ void prep_hin(const float* __restrict__ x, const int* __restrict__ tids,
                         const float* __restrict__ emb) {
    int i = blockIdx.x * blockDim.x + threadIdx.x;
    if (i >= NN * FD) return;
    int n = i / FD, c = i % FD;
    g_hin[i] = (c < 128) ? x[n * 128 + c] : emb[tids[n] * 32 + (c - 128)];
}

__global__ void prep_w(const float* __restrict__ Wih,
                       const float* __restrict__ bih, const float* __restrict__ bhh,
                       const float* __restrict__ Wl,  const float* __restrict__ Wr) {
    int i = blockIdx.x * blockDim.x + threadIdx.x;
    if (i < KHH * HD * 4) {
        int g = i & 3, m = (i >> 2) % HD, k = (i >> 2) / HD;
        g_WihP[i] = Wih[(g * HD + m) * FD + k];
    }
    if (i < GD) {
        int m = i >> 2, g = i & 3;
        g_bias[i] = bih[g * HD + m] + bhh[g * HD + m];
    }
    if (i < KHH * OC) {
        int k = i / OC, j = i % OC;
        g_WlP[i] = Wl[j * FD + k];
        g_WrP[i] = Wr[j * FD + k];
    }
}

// bf16 hi/lo split + transpose of Whh into [pl][q][kc][n][16]
__global__ void prep_wb(const float* __restrict__ Whh) {
    int i = blockIdx.x * blockDim.x + threadIdx.x;
    if (i >= 2 * 4 * 10 * 160 * 16) return;
    int kk = i & 15;
    int n  = (i >> 4) % 160;
    int kc = (i / 2560) % 10;
    int q  = (i / 25600) % 4;
    int pl = i / 102400;
    int k = kc * 16 + kk;
    int gcl = q * 160 + n;
    int m = gcl >> 2, g = gcl & 3;
    float w = Whh[(g * HD + m) * HD + k];
    __nv_bfloat16 hb = __float2bfloat16(w);
    g_Wb[i] = pl ? __float2bfloat16(w - __bfloat162float(hb)) : hb;
}

// ---- prep_PQ: fp32 K=160 GEMM (proven) ----
__device__ __forceinline__ void pstage(const float* gsrc, uint32_t sdst, int tid) {
#pragma unroll
    for (int u = 0; u < 5; u++)
        cp16(sdst + (uint32_t)(tid * 16 + u * 8192), gsrc + tid * 4 + u * 2048);
    cpcommit();
}
__device__ __forceinline__ void pgemm(const float* __restrict__ gW, uint32_t wsbase,
                                      const float* __restrict__ hrow, int tid, int c,
                                      ull accIF[4][5], ull accGO[4][5]) {
    pstage(gW, wsbase, tid);
    pstage(gW + PCHF, wsbase + PCHB, tid);
    for (int ch = 0; ch < PNCH; ch++) {
        if (ch == PNCH - 1) cpwait<0>(); else cpwait<1>();
        __syncthreads();
        const uint32_t wb0 = wsbase + (uint32_t)(ch & 1) * PCHB;
#pragma unroll
        for (int kq = 0; kq < 4; kq++) {
            float4 a4[4];
#pragma unroll
            for (int i = 0; i < 4; i++)
                a4[i] = *(const float4*)&hrow[i * KHH + ch * PKC + kq * 4];
#pragma unroll
            for (int k2 = 0; k2 < 4; k2++) {
                ull a2[4];
#pragma unroll
                for (int i = 0; i < 4; i++) {
                    float a = (k2 == 0) ? a4[i].x : (k2 == 1) ? a4[i].y
                             : (k2 == 2) ? a4[i].z : a4[i].w;
                    a2[i] = pack2(a, a);
                }
                const uint32_t wb = wb0 + (uint32_t)((kq * 4 + k2) * 2560 + c * 16);
#pragma unroll
                for (int n = 0; n < 5; n++) {
                    ull wif, wgo;
                    ldsv2(wb + (uint32_t)(n * 512), wif, wgo);
#pragma unroll
                    for (int i = 0; i < 4; i++) {
                        fma2(accIF[i][n], a2[i], wif);
                        fma2(accGO[i][n], a2[i], wgo);
                    }
                }
            }
        }
        __syncthreads();
        if (ch < PNCH - 2) pstage(gW + (ch + 2) * PCHF, wsbase + (uint32_t)(ch & 1) * PCHB, tid);
    }
}

__global__ void __launch_bounds__(PNT, 1)
prep_PQ(const float* __restrict__ bl) {
    extern __shared__ float sm[];
    float* hs = sm;
    const uint32_t sbase = (uint32_t)__cvta_generic_to_shared(sm);
    const uint32_t wsbase = sbase + PTM * KHH * 4;
    const int tid = threadIdx.x, c = tid & 31, warp = tid >> 5;
    const int nodeBase = blockIdx.x * PTM;
    float* hrow = hs + warp * 4 * KHH;

#pragma unroll
    for (int u = 0; u < 5; u++) {
        int idx4 = tid + u * PNT;
        int r = idx4 / 40, col4 = idx4 % 40;
        int node = nodeBase + r; if (node >= NN) node = NN - 1;
        ((float4*)hs)[idx4] = ((const float4*)g_hin)[node * 40 + col4];
    }
    __syncthreads();

    ull accIF[4][5], accGO[4][5];
#pragma unroll
    for (int n = 0; n < 5; n++) {
        float4 b = ((const float4*)g_bias)[n * 32 + c];
#pragma unroll
        for (int i = 0; i < 4; i++) {
            accIF[i][n] = pack2(b.x, b.y);
            accGO[i][n] = pack2(b.z, b.w);
        }
    }
    pgemm(g_WihP, wsbase, hrow, tid, c, accIF, accGO);

#pragma unroll
    for (int i = 0; i < 4; i++) {
        int node = nodeBase + warp * 4 + i;
        if (node < NN) {
#pragma unroll
            for (int n = 0; n < 5; n++) {
                float4 o;
                unpack2(accIF[i][n], o.x, o.y);
                unpack2(accGO[i][n], o.z, o.w);
                ((float4*)g_P)[node * 160 + n * 32 + c] = o;
            }
        }
    }

    __syncthreads();
    float* Wfs = hs + PTM * KHH;
    for (int u = tid; u < KHH * OC / 4; u += PNT)
        ((float4*)Wfs)[u] = ((const float4*)g_WrP)[u];
    __syncthreads();

    float4 q[4];
    float4 blv = ((const float4*)bl)[c];
#pragma unroll
    for (int i = 0; i < 4; i++) q[i] = blv;
    for (int k = 0; k < KHH; k++) {
        float4 w = ((const float4*)Wfs)[k * 32 + c];
#pragma unroll
        for (int i = 0; i < 4; i++) {
            float a = hrow[i * KHH + k];
            q[i].x = fmaf(a, w.x, q[i].x);
            q[i].y = fmaf(a, w.y, q[i].y);
            q[i].z = fmaf(a, w.z, q[i].z);
            q[i].w = fmaf(a, w.w, q[i].w);
        }
    }
#pragma unroll
    for (int i = 0; i < 4; i++) {
        int node = nodeBase + warp * 4 + i;
        if (node < NN) ((float4*)g_Q)[node * 32 + c] = q[i];
    }
}

// ---------------- main MMA recurrence kernel ----------------
// stage = 25600 B (5 kc x 160 n x 16 k bf16)
__device__ __forceinline__ void stageB25(uint32_t sdst, const __nv_bfloat16* g, int tid) {
#pragma unroll
    for (int u = 0; u < 6; u++)
        cp16(sdst + (uint32_t)((tid + u * 256) * 16), g + (tid + u * 256) * 8);
    if (tid < 64) cp16(sdst + (uint32_t)((1536 + tid) * 16), g + (1536 + tid) * 8);
    cpcommit();
}

// 5-kc MMA pass over one B block
__device__ __forceinline__ void mma5(uint32_t aPl, uint32_t bB, int kcb,
                                     int mg, int ng, int r8, int q2,
                                     float acc[2][5][4]) {
#pragma unroll
    for (int kcl = 0; kcl < 5; kcl++) {
        uint32_t af[2][4];
#pragma unroll
        for (int mt = 0; mt < 2; mt++) {
            uint32_t a0 = aPl + (uint32_t)(((mg * 32 + mt * 16 + r8) * 168
                                            + (kcb + kcl) * 16 + q2 * 2) * 2);
            af[mt][0] = lds32(a0);
            af[mt][1] = lds32(a0 + 2688);
            af[mt][2] = lds32(a0 + 16);
            af[mt][3] = lds32(a0 + 2704);
        }
#pragma unroll
        for (int nt = 0; nt < 5; nt++) {
            uint32_t ba = bB + (uint32_t)((kcl * 2560 + (ng * 40 + nt * 8 + r8) * 16
                                           + q2 * 2) * 2);
            uint32_t b0 = lds32(ba), b1 = lds32(ba + 16);
            mma_bf16(acc[0][nt], af[0], b0, b1);
            mma_bf16(acc[1][nt], af[1], b0, b1);
        }
    }
}

__global__ void __launch_bounds__(NT)
lstm_main(const int* __restrict__ esrc, float* __restrict__ out) {
    extern __shared__ char smraw[];
    __nv_bfloat16* hB = (__nv_bfloat16*)smraw;       // [2buf][2pl][64][168]
    float* cst = (float*)(smraw + SM_CST);
    int*   srcS = (int*)(smraw + SM_SRC);            // [2][64]
    const uint32_t sbase = (uint32_t)__cvta_generic_to_shared(smraw);

    const int tid = threadIdx.x, lane = tid & 31, warp = tid >> 5;
    const int q2 = lane & 3, r8 = lane >> 2;
    const int mg = warp & 1, ng = warp >> 1;
    const int nodeBase = blockIdx.x * TM;

    for (int i = tid; i < 21504; i += NT) hB[i] = __float2bfloat16(0.f);
#pragma unroll
    for (int j = 0; j < 40; j++) cst[j * NT + tid] = 0.f;
    if (tid < TM) {
        int node = nodeBase + tid; if (node >= NN) node = NN - 1;
        srcS[tid] = esrc[node * DEG];
    }
    stageB25(sbase + SM_B, g_Wb, tid);                   // s=0: q0 hi half0
    stageB25(sbase + SM_B + 25600, g_Wb + 12800, tid);   // s=1: q0 hi half1

    float acc[2][5][4];

    for (int s = 0; s < 256; s++) {
        const int t = s >> 4, r = s & 15, q = r >> 2, ph = r & 3;
        if (s == 255) cpwait<0>(); else cpwait<1>();
        __syncthreads();
        const uint32_t hRd = sbase + (uint32_t)(t & 1) * HBUFB;
        const uint32_t bB = sbase + SM_B + (uint32_t)(s & 1) * 25600;
        const int kcb = (ph & 1) * 5;

        if (ph == 0) {
            // acc init from P (biases folded)
            const int gb = q * 160 + ng * 40 + q2 * 2;
            const int* sp = srcS + (t & 1) * 64;
#pragma unroll
            for (int mt = 0; mt < 2; mt++) {
                int rr = mg * 32 + mt * 16 + r8;
                const float* p0 = g_P + (size_t)sp[rr] * 640 + gb;
                const float* p8 = g_P + (size_t)sp[rr + 8] * 640 + gb;
#pragma unroll
                for (int nt = 0; nt < 5; nt++) {
                    float2 v0 = *(const float2*)(p0 + nt * 8);
                    float2 v8 = *(const float2*)(p8 + nt * 8);
                    acc[mt][nt][0] = v0.x; acc[mt][nt][1] = v0.y;
                    acc[mt][nt][2] = v8.x; acc[mt][nt][3] = v8.y;
                }
            }
            if (q == 0 && t < DEG - 1 && tid < TM) {
                int node = nodeBase + tid; if (node >= NN) node = NN - 1;
                srcS[((t + 1) & 1) * 64 + tid] = esrc[node * DEG + t + 1];
            }
        }
        if (ph < 2) {
            mma5(hRd,          bB, kcb, mg, ng, r8, q2, acc);   // A-hi x B-hi
            mma5(hRd + HPLANE, bB, kcb, mg, ng, r8, q2, acc);   // A-lo x B-hi
        } else {
            mma5(hRd,          bB, kcb, mg, ng, r8, q2, acc);   // A-hi x B-lo
        }
        if (ph == 3) {
            // pointwise; lane pair (i,f)|(g,o) exchange via shfl_xor(1)
            __nv_bfloat16* hWr = hB + ((t + 1) & 1) * 21504;
#pragma unroll
            for (int mt = 0; mt < 2; mt++) {
                int rw = mg * 32 + mt * 16 + r8 + ((q2 & 1) ? 8 : 0);
#pragma unroll
                for (int nt = 0; nt < 5; nt++) {
                    float ox = __shfl_xor_sync(0xffffffff, acc[mt][nt][0], 1);
                    float oy = __shfl_xor_sync(0xffffffff, acc[mt][nt][1], 1);
                    float oz = __shfl_xor_sync(0xffffffff, acc[mt][nt][2], 1);
                    float ow = __shfl_xor_sync(0xffffffff, acc[mt][nt][3], 1);
                    float gi, gf, gg, go;
                    if (!(q2 & 1)) { gi = acc[mt][nt][0]; gf = acc[mt][nt][1]; gg = ox; go = oy; }
                    else           { gi = oz; gf = ow; gg = acc[mt][nt][2]; go = acc[mt][nt][3]; }
                    int m = q * 40 + ng * 10 + nt * 2 + (q2 >> 1);
                    int slot = q * 10 + mt * 5 + nt;
                    float cv = sigm(gf) * cst[slot * NT + tid] + sigm(gi) * tanhfast(gg);
                    cst[slot * NT + tid] = cv;
                    float hv = sigm(go) * tanhfast(cv);
                    __nv_bfloat16 hh = __float2bfloat16(hv);
                    hWr[rw * 168 + m] = hh;
                    hWr[10752 + rw * 168 + m] = __float2bfloat16(hv - __bfloat162float(hh));
                }
            }
        }
        __syncthreads();
        if (s + 2 < 256) {
            int r2 = (s + 2) & 15;
            int qq = r2 >> 2, pp = r2 & 3;
            const __nv_bfloat16* src = g_Wb + (pp >= 2 ? 102400 : 0) + qq * 25600
                                       + (pp & 1) * 12800;
            stageB25(sbase + SM_B + (uint32_t)(s & 1) * 25600, src, tid);
        }
    }

    // ---- final layer: out = relu(Q[node] + h @ Wl^T); h last in buf0
    __syncthreads();
    const __nv_bfloat16* hf = hB;
    const __nv_bfloat16* hl = hB + 10752;
#pragma unroll
    for (int rr = 0; rr < 8; rr++) {
        int row = warp * 8 + rr;
        int node = nodeBase + row;
        int nc = node < NN ? node : NN - 1;
        float4 qv = ((const float4*)g_Q)[nc * 32 + lane];
        for (int k = 0; k < KHH; k++) {
            float a = __bfloat162float(hf[row * 168 + k]) +
                      __bfloat162float(hl[row * 168 + k]);
            float4 w = *(const float4*)&g_WlP[k * OC + lane * 4];
            qv.x = fmaf(a, w.x, qv.x);
            qv.y = fmaf(a, w.y, qv.y);
            qv.z = fmaf(a, w.z, qv.z);
            qv.w = fmaf(a, w.w, qv.w);
        }
        if (node < NN) {
            float4 o;
            o.x = fmaxf(qv.x, 0.f); o.y = fmaxf(qv.y, 0.f);
            o.z = fmaxf(qv.z, 0.f); o.w = fmaxf(qv.w, 0.f);
            ((float4*)out)[node * 32 + lane] = o;
        }
    }
}

// ---------------- launch ----------------
extern "C" void kernel_launch(void* const* d_in, const int* in_sizes, int n_in,
                              void* d_out, int out_size) {
    const float* x    = (const float*)d_in[0];
    const int*   tids = (const int*)  d_in[1];
    const int*   eidx = (const int*)  d_in[2];
    const float* emb  = (const float*)d_in[3];
    const float* Wih  = (const float*)d_in[4];
    const float* Whh  = (const float*)d_in[5];
    const float* bih  = (const float*)d_in[6];
    const float* bhh  = (const float*)d_in[7];
    const float* Wl   = (const float*)d_in[8];
    const float* bl   = (const float*)d_in[9];
    const float* Wr   = (const float*)d_in[10];
    float* out = (float*)d_out;

    static bool attr_done = false;
    if (!attr_done) {
        cudaFuncSetAttribute(prep_PQ, cudaFuncAttributeMaxDynamicSharedMemorySize,
                             PTM * KHH * 4 + 2 * PCHB);
        cudaFuncSetAttribute(lstm_main, cudaFuncAttributeMaxDynamicSharedMemorySize,
                             SM_MAIN);
        attr_done = true;
    }

    prep_hin<<<(NN * FD + 255) / 256, 256>>>(x, tids, emb);
    prep_w<<<(KHH * HD * 4 + 255) / 256, 256>>>(Wih, bih, bhh, Wl, Wr);
    prep_wb<<<(2 * 4 * 10 * 160 * 16 + 255) / 256, 256>>>(Whh);
    prep_PQ<<<(NN + PTM - 1) / PTM, PNT, PTM * KHH * 4 + 2 * PCHB>>>(bl);
    lstm_main<<<(NN + TM - 1) / TM, NT, SM_MAIN>>>(eidx, out);
}

// round 11
// speedup vs baseline: 1.4874x; 1.4874x over previous
#include <cuda_runtime.h>
#include <cuda_bf16.h>
#include <cstdint>

#define NN   50000
#define DEG  16
#define FD   160
#define HD   160
#define GD   640
#define OC   128
#define KHH  160

// prep (fp32) config — proven machinery
#define PTM  64
#define PNT  512
#define PKC  16
#define PNCH (KHH/PKC)
#define PCHF (PKC*GD)
#define PCHB (PCHF*4)

// main MMA kernel config
#define TM   64
#define NT   256
#define HPLANE 21504               // bytes per h plane (64*168*2)
#define HBUFB  43008               // bytes per h buffer (2 planes)
#define SM_B   86016               // B double buffer: 2 x 38400 (48B padded rows)
#define BSTG   38400
#define SM_CST 162816              // 40*256*4
#define SM_SRC 203776              // 2*64 ints
#define SM_MAIN 204288

typedef unsigned long long ull;

// ---------------- device scratch ----------------
__device__ float g_hin[NN * FD];
__device__ float g_WihP[KHH * HD * 4];   // [k][m][4]
__device__ float g_bias[GD];             // [m][4]
__device__ float g_WlP[KHH * OC];
__device__ float g_WrP[KHH * OC];
__device__ float g_P[NN * GD];           // [node][4m+g], biases folded
__device__ float g_Q[NN * OC];
// Whh bf16 split: [pl 2][q 4][kc 10][n 160][16]  (unpadded in gmem)
__device__ __align__(16) __nv_bfloat16 g_Wb[2 * 4 * 10 * 160 * 16];

// ---------------- helpers ----------------
__device__ __forceinline__ ull pack2(float lo, float hi) {
    ull v; asm("mov.b64 %0, {%1, %2};" : "=l"(v) : "f"(lo), "f"(hi)); return v;
}
__device__ __forceinline__ void unpack2(ull v, float& lo, float& hi) {
    asm("mov.b64 {%0, %1}, %2;" : "=f"(lo), "=f"(hi) : "l"(v));
}
__device__ __forceinline__ void fma2(ull& d, ull a, ull b) {
    asm("fma.rn.f32x2 %0, %1, %2, %0;" : "+l"(d) : "l"(a), "l"(b));
}
__device__ __forceinline__ void ldsv2(uint32_t a, ull& x, ull& y) {
    asm("ld.shared.v2.u64 {%0,%1}, [%2];" : "=l"(x), "=l"(y) : "r"(a));
}
__device__ __forceinline__ void ldsm4(uint32_t* r, uint32_t a) {
    asm volatile("ldmatrix.sync.aligned.m8n8.x4.shared.b16 {%0,%1,%2,%3}, [%4];"
                 : "=r"(r[0]), "=r"(r[1]), "=r"(r[2]), "=r"(r[3]) : "r"(a));
}
__device__ __forceinline__ void ldsm2(uint32_t* r, uint32_t a) {
    asm volatile("ldmatrix.sync.aligned.m8n8.x2.shared.b16 {%0,%1}, [%2];"
                 : "=r"(r[0]), "=r"(r[1]) : "r"(a));
}
__device__ __forceinline__ void cp16(uint32_t s, const void* g) {
    asm volatile("cp.async.ca.shared.global [%0], [%1], 16;" :: "r"(s), "l"(g));
}
__device__ __forceinline__ void cpcommit() { asm volatile("cp.async.commit_group;"); }
template<int N> __device__ __forceinline__ void cpwait() {
    asm volatile("cp.async.wait_group %0;" :: "n"(N));
}
__device__ __forceinline__ float sigm(float x) { return __fdividef(1.f, 1.f + __expf(-x)); }
__device__ __forceinline__ float tanhfast(float x) {
    return __fdividef(2.f, 1.f + __expf(-2.f * x)) - 1.f;
}
__device__ __forceinline__ void mma_bf16(float* d, const uint32_t* a, uint32_t b0, uint32_t b1) {
    asm volatile("mma.sync.aligned.m16n8k16.row.col.f32.bf16.bf16.f32 "
                 "{%0,%1,%2,%3}, {%4,%5,%6,%7}, {%8,%9}, {%0,%1,%2,%3};"
                 : "+f"(d[0]), "+f"(d[1]), "+f"(d[2]), "+f"(d[3])
                 : "r"(a[0]), "r"(a[1]), "r"(a[2]), "r"(a[3]), "r"(b0), "r"(b1));
}

// ---------------- prep kernels ----------------
__global__ void prep_hin(const float* __restrict__ x, const int* __restrict__ tids,
                         const float* __restrict__ emb) {
    int i = blockIdx.x * blockDim.x + threadIdx.x;
    if (i >= NN * FD) return;
    int n = i / FD, c = i % FD;
    g_hin[i] = (c < 128) ? x[n * 128 + c] : emb[tids[n] * 32 + (c - 128)];
}

__global__ void prep_w(const float* __restrict__ Wih,
                       const float* __restrict__ bih, const float* __restrict__ bhh,
                       const float* __restrict__ Wl,  const float* __restrict__ Wr) {
    int i = blockIdx.x * blockDim.x + threadIdx.x;
    if (i < KHH * HD * 4) {
        int g = i & 3, m = (i >> 2) % HD, k = (i >> 2) / HD;
        g_WihP[i] = Wih[(g * HD + m) * FD + k];
    }
    if (i < GD) {
        int m = i >> 2, g = i & 3;
        g_bias[i] = bih[g * HD + m] + bhh[g * HD + m];
    }
    if (i < KHH * OC) {
        int k = i / OC, j = i % OC;
        g_WlP[i] = Wl[j * FD + k];
        g_WrP[i] = Wr[j * FD + k];
    }
}

// bf16 hi/lo split + transpose of Whh into [pl][q][kc][n][16]
__global__ void prep_wb(const float* __restrict__ Whh) {
    int i = blockIdx.x * blockDim.x + threadIdx.x;
    if (i >= 2 * 4 * 10 * 160 * 16) return;
    int kk = i & 15;
    int n  = (i >> 4) % 160;
    int kc = (i / 2560) % 10;
    int q  = (i / 25600) % 4;
    int pl = i / 102400;
    int k = kc * 16 + kk;
    int gcl = q * 160 + n;
    int m = gcl >> 2, g = gcl & 3;
    float w = Whh[(g * HD + m) * HD + k];
    __nv_bfloat16 hb = __float2bfloat16(w);
    g_Wb[i] = pl ? __float2bfloat16(w - __bfloat162float(hb)) : hb;
}

// ---- prep_PQ: fp32 K=160 GEMM (proven) ----
__device__ __forceinline__ void pstage(const float* gsrc, uint32_t sdst, int tid) {
#pragma unroll
    for (int u = 0; u < 5; u++)
        cp16(sdst + (uint32_t)(tid * 16 + u * 8192), gsrc + tid * 4 + u * 2048);
    cpcommit();
}
__device__ __forceinline__ void pgemm(const float* __restrict__ gW, uint32_t wsbase,
                                      const float* __restrict__ hrow, int tid, int c,
                                      ull accIF[4][5], ull accGO[4][5]) {
    pstage(gW, wsbase, tid);
    pstage(gW + PCHF, wsbase + PCHB, tid);
    for (int ch = 0; ch < PNCH; ch++) {
        if (ch == PNCH - 1) cpwait<0>(); else cpwait<1>();
        __syncthreads();
        const uint32_t wb0 = wsbase + (uint32_t)(ch & 1) * PCHB;
#pragma unroll
        for (int kq = 0; kq < 4; kq++) {
            float4 a4[4];
#pragma unroll
            for (int i = 0; i < 4; i++)
                a4[i] = *(const float4*)&hrow[i * KHH + ch * PKC + kq * 4];
#pragma unroll
            for (int k2 = 0; k2 < 4; k2++) {
                ull a2[4];
#pragma unroll
                for (int i = 0; i < 4; i++) {
                    float a = (k2 == 0) ? a4[i].x : (k2 == 1) ? a4[i].y
                             : (k2 == 2) ? a4[i].z : a4[i].w;
                    a2[i] = pack2(a, a);
                }
                const uint32_t wb = wb0 + (uint32_t)((kq * 4 + k2) * 2560 + c * 16);
#pragma unroll
                for (int n = 0; n < 5; n++) {
                    ull wif, wgo;
                    ldsv2(wb + (uint32_t)(n * 512), wif, wgo);
#pragma unroll
                    for (int i = 0; i < 4; i++) {
                        fma2(accIF[i][n], a2[i], wif);
                        fma2(accGO[i][n], a2[i], wgo);
                    }
                }
            }
        }
        __syncthreads();
        if (ch < PNCH - 2) pstage(gW + (ch + 2) * PCHF, wsbase + (uint32_t)(ch & 1) * PCHB, tid);
    }
}

__global__ void __launch_bounds__(PNT, 1)
prep_PQ(const float* __restrict__ bl) {
    extern __shared__ float sm[];
    float* hs = sm;
    const uint32_t sbase = (uint32_t)__cvta_generic_to_shared(sm);
    const uint32_t wsbase = sbase + PTM * KHH * 4;
    const int tid = threadIdx.x, c = tid & 31, warp = tid >> 5;
    const int nodeBase = blockIdx.x * PTM;
    float* hrow = hs + warp * 4 * KHH;

#pragma unroll
    for (int u = 0; u < 5; u++) {
        int idx4 = tid + u * PNT;
        int r = idx4 / 40, col4 = idx4 % 40;
        int node = nodeBase + r; if (node >= NN) node = NN - 1;
        ((float4*)hs)[idx4] = ((const float4*)g_hin)[node * 40 + col4];
    }
    __syncthreads();

    ull accIF[4][5], accGO[4][5];
#pragma unroll
    for (int n = 0; n < 5; n++) {
        float4 b = ((const float4*)g_bias)[n * 32 + c];
#pragma unroll
        for (int i = 0; i < 4; i++) {
            accIF[i][n] = pack2(b.x, b.y);
            accGO[i][n] = pack2(b.z, b.w);
        }
    }
    pgemm(g_WihP, wsbase, hrow, tid, c, accIF, accGO);

#pragma unroll
    for (int i = 0; i < 4; i++) {
        int node = nodeBase + warp * 4 + i;
        if (node < NN) {
#pragma unroll
            for (int n = 0; n < 5; n++) {
                float4 o;
                unpack2(accIF[i][n], o.x, o.y);
                unpack2(accGO[i][n], o.z, o.w);
                ((float4*)g_P)[node * 160 + n * 32 + c] = o;
            }
        }
    }

    __syncthreads();
    float* Wfs = hs + PTM * KHH;
    for (int u = tid; u < KHH * OC / 4; u += PNT)
        ((float4*)Wfs)[u] = ((const float4*)g_WrP)[u];
    __syncthreads();

    float4 q[4];
    float4 blv = ((const float4*)bl)[c];
#pragma unroll
    for (int i = 0; i < 4; i++) q[i] = blv;
    for (int k = 0; k < KHH; k++) {
        float4 w = ((const float4*)Wfs)[k * 32 + c];
#pragma unroll
        for (int i = 0; i < 4; i++) {
            float a = hrow[i * KHH + k];
            q[i].x = fmaf(a, w.x, q[i].x);
            q[i].y = fmaf(a, w.y, q[i].y);
            q[i].z = fmaf(a, w.z, q[i].z);
            q[i].w = fmaf(a, w.w, q[i].w);
        }
    }
#pragma unroll
    for (int i = 0; i < 4; i++) {
        int node = nodeBase + warp * 4 + i;
        if (node < NN) ((float4*)g_Q)[node * 32 + c] = q[i];
    }
}

// ---------------- main MMA recurrence kernel ----------------
// stage = 25600B data (5 kc x 160 n x 16 k bf16) scattered into 48B-padded rows
__device__ __forceinline__ void stageB38(uint32_t sdst, const __nv_bfloat16* g, int tid) {
#pragma unroll
    for (int u = 0; u < 6; u++) {
        int idx = tid + u * 256;                 // 0..1535
        int row = idx >> 1, ch = idx & 1;
        cp16(sdst + (uint32_t)(row * 48 + ch * 16), (const char*)g + (size_t)idx * 16);
    }
    if (tid < 64) {
        int idx = 1536 + tid;
        int row = idx >> 1, ch = idx & 1;
        cp16(sdst + (uint32_t)(row * 48 + ch * 16), (const char*)g + (size_t)idx * 16);
    }
    cpcommit();
}

// 5-kc MMA pass: A via ldmatrix.x4 (2 mt), B via ldmatrix.x2 (5 nt)
__device__ __forceinline__ void mma5(uint32_t aBase, uint32_t bBase, float acc[2][5][4]) {
#pragma unroll
    for (int kcl = 0; kcl < 5; kcl++) {
        uint32_t af[2][4];
        ldsm4(af[0], aBase + (uint32_t)(kcl * 32));
        ldsm4(af[1], aBase + (uint32_t)(16 * 336 + kcl * 32));
#pragma unroll
        for (int nt = 0; nt < 5; nt++) {
            uint32_t b[2];
            ldsm2(b, bBase + (uint32_t)(kcl * 7680 + nt * 384));
            mma_bf16(acc[0][nt], af[0], b[0], b[1]);
            mma_bf16(acc[1][nt], af[1], b[0], b[1]);
        }
    }
}

__global__ void __launch_bounds__(NT)
lstm_main(const int* __restrict__ esrc, float* __restrict__ out) {
    extern __shared__ char smraw[];
    __nv_bfloat16* hB = (__nv_bfloat16*)smraw;       // [2buf][2pl][64][168]
    float* cst = (float*)(smraw + SM_CST);
    int*   srcS = (int*)(smraw + SM_SRC);            // [2][64]
    const uint32_t sbase = (uint32_t)__cvta_generic_to_shared(smraw);

    const int tid = threadIdx.x, lane = tid & 31, warp = tid >> 5;
    const int q2 = lane & 3, r8 = lane >> 2;
    const int mg = warp & 1, ng = warp >> 1;
    const int lrow = lane & 15, lkoff = (lane >> 4) * 16;
    const int nodeBase = blockIdx.x * TM;

    for (int i = tid; i < 21504; i += NT) hB[i] = __float2bfloat16(0.f);
#pragma unroll
    for (int j = 0; j < 40; j++) cst[j * NT + tid] = 0.f;
    if (tid < TM) {
        int node = nodeBase + tid; if (node >= NN) node = NN - 1;
        srcS[tid] = esrc[node * DEG];
    }
    stageB38(sbase + SM_B, g_Wb, tid);                   // s=0: q0 hi half0
    stageB38(sbase + SM_B + BSTG, g_Wb + 12800, tid);    // s=1: q0 hi half1

    float acc[2][5][4];

    for (int s = 0; s < 256; s++) {
        const int t = s >> 4, r = s & 15, q = r >> 2, ph = r & 3;
        if (s == 255) cpwait<0>(); else cpwait<1>();
        __syncthreads();
        const uint32_t hRd = sbase + (uint32_t)(t & 1) * HBUFB;
        const uint32_t bB = sbase + SM_B + (uint32_t)(s & 1) * BSTG;
        const int kcb = (ph & 1) * 5;

        if (ph == 0) {
            // acc init from P (biases folded)
            const int gb = q * 160 + ng * 40 + q2 * 2;
            const int* sp = srcS + (t & 1) * 64;
#pragma unroll
            for (int mt = 0; mt < 2; mt++) {
                int rr = mg * 32 + mt * 16 + r8;
                const float* p0 = g_P + (size_t)sp[rr] * 640 + gb;
                const float* p8 = g_P + (size_t)sp[rr + 8] * 640 + gb;
#pragma unroll
                for (int nt = 0; nt < 5; nt++) {
                    float2 v0 = *(const float2*)(p0 + nt * 8);
                    float2 v8 = *(const float2*)(p8 + nt * 8);
                    acc[mt][nt][0] = v0.x; acc[mt][nt][1] = v0.y;
                    acc[mt][nt][2] = v8.x; acc[mt][nt][3] = v8.y;
                }
            }
            if (q == 0 && t < DEG - 1 && tid < TM) {
                int node = nodeBase + tid; if (node >= NN) node = NN - 1;
                srcS[((t + 1) & 1) * 64 + tid] = esrc[node * DEG + t + 1];
            }
        }

        const uint32_t aB0 = hRd + (uint32_t)((mg * 32 + lrow) * 336 + kcb * 32 + lkoff);
        const uint32_t bB0 = bB + (uint32_t)((ng * 40 + (lane & 7)) * 48
                                             + ((lane >> 3) & 1) * 16);
        if (ph < 2) {
            mma5(aB0,          bB0, acc);   // A-hi x B-hi
            mma5(aB0 + HPLANE, bB0, acc);   // A-lo x B-hi
        } else {
            mma5(aB0,          bB0, acc);   // A-hi x B-lo
        }

        if (ph == 3) {
            // pointwise; lane pair (i,f)|(g,o) exchange via shfl_xor(1)
            __nv_bfloat16* hWr = hB + ((t + 1) & 1) * 21504;
#pragma unroll
            for (int mt = 0; mt < 2; mt++) {
                int rw = mg * 32 + mt * 16 + r8 + ((q2 & 1) ? 8 : 0);
#pragma unroll
                for (int nt = 0; nt < 5; nt++) {
                    float ox = __shfl_xor_sync(0xffffffff, acc[mt][nt][0], 1);
                    float oy = __shfl_xor_sync(0xffffffff, acc[mt][nt][1], 1);
                    float oz = __shfl_xor_sync(0xffffffff, acc[mt][nt][2], 1);
                    float ow = __shfl_xor_sync(0xffffffff, acc[mt][nt][3], 1);
                    float gi, gf, gg, go;
                    if (!(q2 & 1)) { gi = acc[mt][nt][0]; gf = acc[mt][nt][1]; gg = ox; go = oy; }
                    else           { gi = oz; gf = ow; gg = acc[mt][nt][2]; go = acc[mt][nt][3]; }
                    int m = q * 40 + ng * 10 + nt * 2 + (q2 >> 1);
                    int slot = q * 10 + mt * 5 + nt;
                    float cv = sigm(gf) * cst[slot * NT + tid] + sigm(gi) * tanhfast(gg);
                    cst[slot * NT + tid] = cv;
                    float hv = sigm(go) * tanhfast(cv);
                    __nv_bfloat16 hh = __float2bfloat16(hv);
                    hWr[rw * 168 + m] = hh;
                    hWr[10752 + rw * 168 + m] = __float2bfloat16(hv - __bfloat162float(hh));
                }
            }
        }
        __syncthreads();
        if (s + 2 < 256) {
            int r2 = (s + 2) & 15;
            int qq = r2 >> 2, pp = r2 & 3;
            const __nv_bfloat16* src = g_Wb + (pp >= 2 ? 102400 : 0) + qq * 25600
                                       + (pp & 1) * 12800;
            stageB38(sbase + SM_B + (uint32_t)(s & 1) * BSTG, src, tid);
        }
    }

    // ---- final layer: out = relu(Q[node] + h @ Wl^T); h last in buf0
    __syncthreads();
    const __nv_bfloat16* hf = hB;
    const __nv_bfloat16* hl = hB + 10752;
#pragma unroll
    for (int rr = 0; rr < 8; rr++) {
        int row = warp * 8 + rr;
        int node = nodeBase + row;
        int nc = node < NN ? node : NN - 1;
        float4 qv = ((const float4*)g_Q)[nc * 32 + lane];
        for (int k = 0; k < KHH; k++) {
            float a = __bfloat162float(hf[row * 168 + k]) +
                      __bfloat162float(hl[row * 168 + k]);
            float4 w = *(const float4*)&g_WlP[k * OC + lane * 4];
            qv.x = fmaf(a, w.x, qv.x);
            qv.y = fmaf(a, w.y, qv.y);
            qv.z = fmaf(a, w.z, qv.z);
            qv.w = fmaf(a, w.w, qv.w);
        }
        if (node < NN) {
            float4 o;
            o.x = fmaxf(qv.x, 0.f); o.y = fmaxf(qv.y, 0.f);
            o.z = fmaxf(qv.z, 0.f); o.w = fmaxf(qv.w, 0.f);
            ((float4*)out)[node * 32 + lane] = o;
        }
    }
}

// ---------------- launch ----------------
extern "C" void kernel_launch(void* const* d_in, const int* in_sizes, int n_in,
                              void* d_out, int out_size) {
    const float* x    = (const float*)d_in[0];
    const int*   tids = (const int*)  d_in[1];
    const int*   eidx = (const int*)  d_in[2];
    const float* emb  = (const float*)d_in[3];
    const float* Wih  = (const float*)d_in[4];
    const float* Whh  = (const float*)d_in[5];
    const float* bih  = (const float*)d_in[6];
    const float* bhh  = (const float*)d_in[7];
    const float* Wl   = (const float*)d_in[8];
    const float* bl   = (const float*)d_in[9];
    const float* Wr   = (const float*)d_in[10];
    float* out = (float*)d_out;

    static bool attr_done = false;
    if (!attr_done) {
        cudaFuncSetAttribute(prep_PQ, cudaFuncAttributeMaxDynamicSharedMemorySize,
                             PTM * KHH * 4 + 2 * PCHB);
        cudaFuncSetAttribute(lstm_main, cudaFuncAttributeMaxDynamicSharedMemorySize,
                             SM_MAIN);
        attr_done = true;
    }

    prep_hin<<<(NN * FD + 255) / 256, 256>>>(x, tids, emb);
    prep_w<<<(KHH * HD * 4 + 255) / 256, 256>>>(Wih, bih, bhh, Wl, Wr);
    prep_wb<<<(2 * 4 * 10 * 160 * 16 + 255) / 256, 256>>>(Whh);
    prep_PQ<<<(NN + PTM - 1) / PTM, PNT, PTM * KHH * 4 + 2 * PCHB>>>(bl);
    lstm_main<<<(NN + TM - 1) / TM, NT, SM_MAIN>>>(eidx, out);
}

// round 12
// speedup vs baseline: 1.4950x; 1.0052x over previous
#include <cuda_runtime.h>
#include <cuda_bf16.h>
#include <cstdint>

#define NN   50000
#define DEG  16
#define FD   160
#define HD   160
#define GD   640
#define OC   128
#define KHH  160

// prep (fp32) config — proven machinery
#define PTM  64
#define PNT  512
#define PKC  16
#define PNCH (KHH/PKC)
#define PCHF (PKC*GD)
#define PCHB (PCHF*4)

// main MMA kernel config
#define TM   64
#define NT   256
#define HPLANE 21504               // bytes per h plane (64*168*2)
#define HBUFB  43008               // bytes per h buffer (2 planes)
#define SM_B   86016               // B double buffer: 2 x 38400 (48B padded rows)
#define BSTG   38400
#define SM_CST 162816              // 40*256*4
#define SM_SRC 203776              // 2*64 ints
#define SM_MAIN 204288

typedef unsigned long long ull;

// ---------------- device scratch ----------------
__device__ float g_hin[NN * FD];
__device__ float g_WihP[KHH * HD * 4];   // [k][m][4]
__device__ float g_bias[GD];             // [m][4]
__device__ float g_WlP[KHH * OC];
__device__ float g_WrP[KHH * OC];
__device__ float g_P[NN * GD];           // [node][4m+g], biases folded
__device__ float g_Q[NN * OC];
// Whh bf16 split: [pl 2][q 4][kc 10][n 160][16]  (unpadded in gmem)
__device__ __align__(16) __nv_bfloat16 g_Wb[2 * 4 * 10 * 160 * 16];

// ---------------- helpers ----------------
__device__ __forceinline__ ull pack2(float lo, float hi) {
    ull v; asm("mov.b64 %0, {%1, %2};" : "=l"(v) : "f"(lo), "f"(hi)); return v;
}
__device__ __forceinline__ void unpack2(ull v, float& lo, float& hi) {
    asm("mov.b64 {%0, %1}, %2;" : "=f"(lo), "=f"(hi) : "l"(v));
}
__device__ __forceinline__ void fma2(ull& d, ull a, ull b) {
    asm("fma.rn.f32x2 %0, %1, %2, %0;" : "+l"(d) : "l"(a), "l"(b));
}
__device__ __forceinline__ void ldsv2(uint32_t a, ull& x, ull& y) {
    asm("ld.shared.v2.u64 {%0,%1}, [%2];" : "=l"(x), "=l"(y) : "r"(a));
}
__device__ __forceinline__ void ldsm4(uint32_t* r, uint32_t a) {
    asm volatile("ldmatrix.sync.aligned.m8n8.x4.shared.b16 {%0,%1,%2,%3}, [%4];"
                 : "=r"(r[0]), "=r"(r[1]), "=r"(r[2]), "=r"(r[3]) : "r"(a));
}
__device__ __forceinline__ void ldsm2(uint32_t* r, uint32_t a) {
    asm volatile("ldmatrix.sync.aligned.m8n8.x2.shared.b16 {%0,%1}, [%2];"
                 : "=r"(r[0]), "=r"(r[1]) : "r"(a));
}
__device__ __forceinline__ void cp16(uint32_t s, const void* g) {
    asm volatile("cp.async.ca.shared.global [%0], [%1], 16;" :: "r"(s), "l"(g));
}
__device__ __forceinline__ void cpcommit() { asm volatile("cp.async.commit_group;"); }
template<int N> __device__ __forceinline__ void cpwait() {
    asm volatile("cp.async.wait_group %0;" :: "n"(N));
}
__device__ __forceinline__ float sigm(float x) { return __fdividef(1.f, 1.f + __expf(-x)); }
__device__ __forceinline__ float tanhfast(float x) {
    return __fdividef(2.f, 1.f + __expf(-2.f * x)) - 1.f;
}
__device__ __forceinline__ void mma_bf16(float* d, const uint32_t* a, uint32_t b0, uint32_t b1) {
    asm volatile("mma.sync.aligned.m16n8k16.row.col.f32.bf16.bf16.f32 "
                 "{%0,%1,%2,%3}, {%4,%5,%6,%7}, {%8,%9}, {%0,%1,%2,%3};"
                 : "+f"(d[0]), "+f"(d[1]), "+f"(d[2]), "+f"(d[3])
                 : "r"(a[0]), "r"(a[1]), "r"(a[2]), "r"(a[3]), "r"(b0), "r"(b1));
}

// ---------------- prep kernels ----------------
__global__ void prep_hin(const float* __restrict__ x, const int* __restrict__ tids,
                         const float* __restrict__ emb) {
    int i = blockIdx.x * blockDim.x + threadIdx.x;
    if (i >= NN * FD) return;
    int n = i / FD, c = i % FD;
    g_hin[i] = (c < 128) ? x[n * 128 + c] : emb[tids[n] * 32 + (c - 128)];
}

// prep_w now also builds the bf16 hi/lo split of Whh (merged prep_wb)
__global__ void prep_w(const float* __restrict__ Wih, const float* __restrict__ Whh,
                       const float* __restrict__ bih, const float* __restrict__ bhh,
                       const float* __restrict__ Wl,  const float* __restrict__ Wr) {
    int i = blockIdx.x * blockDim.x + threadIdx.x;
    if (i < KHH * HD * 4) {
        int g = i & 3, m = (i >> 2) % HD, k = (i >> 2) / HD;
        g_WihP[i] = Wih[(g * HD + m) * FD + k];
    }
    if (i < GD) {
        int m = i >> 2, g = i & 3;
        g_bias[i] = bih[g * HD + m] + bhh[g * HD + m];
    }
    if (i < KHH * OC) {
        int k = i / OC, j = i % OC;
        g_WlP[i] = Wl[j * FD + k];
        g_WrP[i] = Wr[j * FD + k];
    }
    if (i < 2 * 4 * 10 * 160 * 16) {
        int kk = i & 15;
        int n  = (i >> 4) % 160;
        int kc = (i / 2560) % 10;
        int q  = (i / 25600) % 4;
        int pl = i / 102400;
        int k = kc * 16 + kk;
        int gcl = q * 160 + n;
        int m = gcl >> 2, g = gcl & 3;
        float w = Whh[(g * HD + m) * HD + k];
        __nv_bfloat16 hb = __float2bfloat16(w);
        g_Wb[i] = pl ? __float2bfloat16(w - __bfloat162float(hb)) : hb;
    }
}

// ---- prep_PQ: fp32 K=160 GEMM (proven) ----
__device__ __forceinline__ void pstage(const float* gsrc, uint32_t sdst, int tid) {
#pragma unroll
    for (int u = 0; u < 5; u++)
        cp16(sdst + (uint32_t)(tid * 16 + u * 8192), gsrc + tid * 4 + u * 2048);
    cpcommit();
}
__device__ __forceinline__ void pgemm(const float* __restrict__ gW, uint32_t wsbase,
                                      const float* __restrict__ hrow, int tid, int c,
                                      ull accIF[4][5], ull accGO[4][5]) {
    pstage(gW, wsbase, tid);
    pstage(gW + PCHF, wsbase + PCHB, tid);
    for (int ch = 0; ch < PNCH; ch++) {
        if (ch == PNCH - 1) cpwait<0>(); else cpwait<1>();
        __syncthreads();
        const uint32_t wb0 = wsbase + (uint32_t)(ch & 1) * PCHB;
#pragma unroll
        for (int kq = 0; kq < 4; kq++) {
            float4 a4[4];
#pragma unroll
            for (int i = 0; i < 4; i++)
                a4[i] = *(const float4*)&hrow[i * KHH + ch * PKC + kq * 4];
#pragma unroll
            for (int k2 = 0; k2 < 4; k2++) {
                ull a2[4];
#pragma unroll
                for (int i = 0; i < 4; i++) {
                    float a = (k2 == 0) ? a4[i].x : (k2 == 1) ? a4[i].y
                             : (k2 == 2) ? a4[i].z : a4[i].w;
                    a2[i] = pack2(a, a);
                }
                const uint32_t wb = wb0 + (uint32_t)((kq * 4 + k2) * 2560 + c * 16);
#pragma unroll
                for (int n = 0; n < 5; n++) {
                    ull wif, wgo;
                    ldsv2(wb + (uint32_t)(n * 512), wif, wgo);
#pragma unroll
                    for (int i = 0; i < 4; i++) {
                        fma2(accIF[i][n], a2[i], wif);
                        fma2(accGO[i][n], a2[i], wgo);
                    }
                }
            }
        }
        __syncthreads();
        if (ch < PNCH - 2) pstage(gW + (ch + 2) * PCHF, wsbase + (uint32_t)(ch & 1) * PCHB, tid);
    }
}

__global__ void __launch_bounds__(PNT, 1)
prep_PQ(const float* __restrict__ bl) {
    extern __shared__ float sm[];
    float* hs = sm;
    const uint32_t sbase = (uint32_t)__cvta_generic_to_shared(sm);
    const uint32_t wsbase = sbase + PTM * KHH * 4;
    const int tid = threadIdx.x, c = tid & 31, warp = tid >> 5;
    const int nodeBase = blockIdx.x * PTM;
    float* hrow = hs + warp * 4 * KHH;

#pragma unroll
    for (int u = 0; u < 5; u++) {
        int idx4 = tid + u * PNT;
        int r = idx4 / 40, col4 = idx4 % 40;
        int node = nodeBase + r; if (node >= NN) node = NN - 1;
        ((float4*)hs)[idx4] = ((const float4*)g_hin)[node * 40 + col4];
    }
    __syncthreads();

    ull accIF[4][5], accGO[4][5];
#pragma unroll
    for (int n = 0; n < 5; n++) {
        float4 b = ((const float4*)g_bias)[n * 32 + c];
#pragma unroll
        for (int i = 0; i < 4; i++) {
            accIF[i][n] = pack2(b.x, b.y);
            accGO[i][n] = pack2(b.z, b.w);
        }
    }
    pgemm(g_WihP, wsbase, hrow, tid, c, accIF, accGO);

#pragma unroll
    for (int i = 0; i < 4; i++) {
        int node = nodeBase + warp * 4 + i;
        if (node < NN) {
#pragma unroll
            for (int n = 0; n < 5; n++) {
                float4 o;
                unpack2(accIF[i][n], o.x, o.y);
                unpack2(accGO[i][n], o.z, o.w);
                ((float4*)g_P)[node * 160 + n * 32 + c] = o;
            }
        }
    }

    __syncthreads();
    float* Wfs = hs + PTM * KHH;
    for (int u = tid; u < KHH * OC / 4; u += PNT)
        ((float4*)Wfs)[u] = ((const float4*)g_WrP)[u];
    __syncthreads();

    float4 q[4];
    float4 blv = ((const float4*)bl)[c];
#pragma unroll
    for (int i = 0; i < 4; i++) q[i] = blv;
    for (int k = 0; k < KHH; k++) {
        float4 w = ((const float4*)Wfs)[k * 32 + c];
#pragma unroll
        for (int i = 0; i < 4; i++) {
            float a = hrow[i * KHH + k];
            q[i].x = fmaf(a, w.x, q[i].x);
            q[i].y = fmaf(a, w.y, q[i].y);
            q[i].z = fmaf(a, w.z, q[i].z);
            q[i].w = fmaf(a, w.w, q[i].w);
        }
    }
#pragma unroll
    for (int i = 0; i < 4; i++) {
        int node = nodeBase + warp * 4 + i;
        if (node < NN) ((float4*)g_Q)[node * 32 + c] = q[i];
    }
}

// ---------------- main MMA recurrence kernel ----------------
// stage = 25600B data (5 kc x 160 n x 16 k bf16) scattered into 48B-padded rows
__device__ __forceinline__ void stageB38(uint32_t sdst, const __nv_bfloat16* g, int tid) {
#pragma unroll
    for (int u = 0; u < 6; u++) {
        int idx = tid + u * 256;                 // 0..1535
        int row = idx >> 1, ch = idx & 1;
        cp16(sdst + (uint32_t)(row * 48 + ch * 16), (const char*)g + (size_t)idx * 16);
    }
    if (tid < 64) {
        int idx = 1536 + tid;
        int row = idx >> 1, ch = idx & 1;
        cp16(sdst + (uint32_t)(row * 48 + ch * 16), (const char*)g + (size_t)idx * 16);
    }
    cpcommit();
}

// 5-kc MMA pass: A via 2x ldmatrix.x4; B via 2x ldmatrix.x4 (nt pairs) + 1x x2
__device__ __forceinline__ void mma5(uint32_t aBase, uint32_t b4, uint32_t b2,
                                     float acc[2][5][4]) {
#pragma unroll
    for (int kcl = 0; kcl < 5; kcl++) {
        uint32_t af[2][4];
        ldsm4(af[0], aBase + (uint32_t)(kcl * 32));
        ldsm4(af[1], aBase + (uint32_t)(16 * 336 + kcl * 32));
        uint32_t b01[4], b23[4], b4r[2];
        ldsm4(b01, b4 + (uint32_t)(kcl * 7680));          // nt0, nt1
        ldsm4(b23, b4 + (uint32_t)(kcl * 7680 + 768));    // nt2, nt3
        ldsm2(b4r, b2 + (uint32_t)(kcl * 7680));          // nt4
        mma_bf16(acc[0][0], af[0], b01[0], b01[1]);
        mma_bf16(acc[1][0], af[1], b01[0], b01[1]);
        mma_bf16(acc[0][1], af[0], b01[2], b01[3]);
        mma_bf16(acc[1][1], af[1], b01[2], b01[3]);
        mma_bf16(acc[0][2], af[0], b23[0], b23[1]);
        mma_bf16(acc[1][2], af[1], b23[0], b23[1]);
        mma_bf16(acc[0][3], af[0], b23[2], b23[3]);
        mma_bf16(acc[1][3], af[1], b23[2], b23[3]);
        mma_bf16(acc[0][4], af[0], b4r[0], b4r[1]);
        mma_bf16(acc[1][4], af[1], b4r[0], b4r[1]);
    }
}

__global__ void __launch_bounds__(NT)
lstm_main(const int* __restrict__ esrc, float* __restrict__ out) {
    extern __shared__ char smraw[];
    __nv_bfloat16* hB = (__nv_bfloat16*)smraw;       // [2buf][2pl][64][168]
    float* cst = (float*)(smraw + SM_CST);
    int*   srcS = (int*)(smraw + SM_SRC);            // [2][64]
    const uint32_t sbase = (uint32_t)__cvta_generic_to_shared(smraw);

    const int tid = threadIdx.x, lane = tid & 31, warp = tid >> 5;
    const int q2 = lane & 3, r8 = lane >> 2;
    const int mg = warp & 1, ng = warp >> 1;
    const int lrow = lane & 15, lkoff = (lane >> 4) * 16;
    const int nodeBase = blockIdx.x * TM;

    for (int i = tid; i < 21504; i += NT) hB[i] = __float2bfloat16(0.f);
#pragma unroll
    for (int j = 0; j < 40; j++) cst[j * NT + tid] = 0.f;
    if (tid < TM) {
        int node = nodeBase + tid; if (node >= NN) node = NN - 1;
        srcS[tid] = esrc[node * DEG];
    }
    stageB38(sbase + SM_B, g_Wb, tid);                   // s=0: q0 hi half0
    stageB38(sbase + SM_B + BSTG, g_Wb + 12800, tid);    // s=1: q0 hi half1

    float acc[2][5][4];

    for (int s = 0; s < 256; s++) {
        const int t = s >> 4, r = s & 15, q = r >> 2, ph = r & 3;
        if (s == 255) cpwait<0>(); else cpwait<1>();
        __syncthreads();
        const uint32_t hRd = sbase + (uint32_t)(t & 1) * HBUFB;
        const uint32_t bB = sbase + SM_B + (uint32_t)(s & 1) * BSTG;
        const int kcb = (ph & 1) * 5;

        if (ph == 0) {
            // acc init from P (biases folded)
            const int gb = q * 160 + ng * 40 + q2 * 2;
            const int* sp = srcS + (t & 1) * 64;
#pragma unroll
            for (int mt = 0; mt < 2; mt++) {
                int rr = mg * 32 + mt * 16 + r8;
                const float* p0 = g_P + (size_t)sp[rr] * 640 + gb;
                const float* p8 = g_P + (size_t)sp[rr + 8] * 640 + gb;
#pragma unroll
                for (int nt = 0; nt < 5; nt++) {
                    float2 v0 = *(const float2*)(p0 + nt * 8);
                    float2 v8 = *(const float2*)(p8 + nt * 8);
                    acc[mt][nt][0] = v0.x; acc[mt][nt][1] = v0.y;
                    acc[mt][nt][2] = v8.x; acc[mt][nt][3] = v8.y;
                }
            }
            if (q == 0 && t < DEG - 1 && tid < TM) {
                int node = nodeBase + tid; if (node >= NN) node = NN - 1;
                srcS[((t + 1) & 1) * 64 + tid] = esrc[node * DEG + t + 1];
            }
        }

        const uint32_t aB0 = hRd + (uint32_t)((mg * 32 + lrow) * 336 + kcb * 32 + lkoff);
        const uint32_t bB4 = bB + (uint32_t)((ng * 40 + ((lane >> 4) & 1) * 8
                                              + (lane & 7)) * 48 + ((lane >> 3) & 1) * 16);
        const uint32_t bB2 = bB + (uint32_t)((ng * 40 + 32 + (lane & 7)) * 48
                                              + ((lane >> 3) & 1) * 16);
        if (ph < 2) {
            mma5(aB0,          bB4, bB2, acc);   // A-hi x B-hi
            mma5(aB0 + HPLANE, bB4, bB2, acc);   // A-lo x B-hi
        } else {
            mma5(aB0,          bB4, bB2, acc);   // A-hi x B-lo
        }

        if (ph == 3) {
            // pointwise; lane pair (i,f)|(g,o) exchange via shfl_xor(1)
            __nv_bfloat16* hWr = hB + ((t + 1) & 1) * 21504;
#pragma unroll
            for (int mt = 0; mt < 2; mt++) {
                int rw = mg * 32 + mt * 16 + r8 + ((q2 & 1) ? 8 : 0);
#pragma unroll
                for (int nt = 0; nt < 5; nt++) {
                    float ox = __shfl_xor_sync(0xffffffff, acc[mt][nt][0], 1);
                    float oy = __shfl_xor_sync(0xffffffff, acc[mt][nt][1], 1);
                    float oz = __shfl_xor_sync(0xffffffff, acc[mt][nt][2], 1);
                    float ow = __shfl_xor_sync(0xffffffff, acc[mt][nt][3], 1);
                    float gi, gf, gg, go;
                    if (!(q2 & 1)) { gi = acc[mt][nt][0]; gf = acc[mt][nt][1]; gg = ox; go = oy; }
                    else           { gi = oz; gf = ow; gg = acc[mt][nt][2]; go = acc[mt][nt][3]; }
                    int m = q * 40 + ng * 10 + nt * 2 + (q2 >> 1);
                    int slot = q * 10 + mt * 5 + nt;
                    float cv = sigm(gf) * cst[slot * NT + tid] + sigm(gi) * tanhfast(gg);
                    cst[slot * NT + tid] = cv;
                    float hv = sigm(go) * tanhfast(cv);
                    __nv_bfloat16 hh = __float2bfloat16(hv);
                    hWr[rw * 168 + m] = hh;
                    hWr[10752 + rw * 168 + m] = __float2bfloat16(hv - __bfloat162float(hh));
                }
            }
        }
        __syncthreads();
        if (s + 2 < 256) {
            int r2 = (s + 2) & 15;
            int qq = r2 >> 2, pp = r2 & 3;
            const __nv_bfloat16* src = g_Wb + (pp >= 2 ? 102400 : 0) + qq * 25600
                                       + (pp & 1) * 12800;
            stageB38(sbase + SM_B + (uint32_t)(s & 1) * BSTG, src, tid);
        }
    }

    // ---- final layer: out = relu(Q[node] + h @ Wl^T); h last in buf0
    __syncthreads();
    const __nv_bfloat16* hf = hB;
    const __nv_bfloat16* hl = hB + 10752;
#pragma unroll
    for (int rr = 0; rr < 8; rr++) {
        int row = warp * 8 + rr;
        int node = nodeBase + row;
        int nc = node < NN ? node : NN - 1;
        float4 qv = ((const float4*)g_Q)[nc * 32 + lane];
        for (int k = 0; k < KHH; k++) {
            float a = __bfloat162float(hf[row * 168 + k]) +
                      __bfloat162float(hl[row * 168 + k]);
            float4 w = *(const float4*)&g_WlP[k * OC + lane * 4];
            qv.x = fmaf(a, w.x, qv.x);
            qv.y = fmaf(a, w.y, qv.y);
            qv.z = fmaf(a, w.z, qv.z);
            qv.w = fmaf(a, w.w, qv.w);
        }
        if (node < NN) {
            float4 o;
            o.x = fmaxf(qv.x, 0.f); o.y = fmaxf(qv.y, 0.f);
            o.z = fmaxf(qv.z, 0.f); o.w = fmaxf(qv.w, 0.f);
            ((float4*)out)[node * 32 + lane] = o;
        }
    }
}

// ---------------- launch ----------------
extern "C" void kernel_launch(void* const* d_in, const int* in_sizes, int n_in,
                              void* d_out, int out_size) {
    const float* x    = (const float*)d_in[0];
    const int*   tids = (const int*)  d_in[1];
    const int*   eidx = (const int*)  d_in[2];
    const float* emb  = (const float*)d_in[3];
    const float* Wih  = (const float*)d_in[4];
    const float* Whh  = (const float*)d_in[5];
    const float* bih  = (const float*)d_in[6];
    const float* bhh  = (const float*)d_in[7];
    const float* Wl   = (const float*)d_in[8];
    const float* bl   = (const float*)d_in[9];
    const float* Wr   = (const float*)d_in[10];
    float* out = (float*)d_out;

    static bool attr_done = false;
    if (!attr_done) {
        cudaFuncSetAttribute(prep_PQ, cudaFuncAttributeMaxDynamicSharedMemorySize,
                             PTM * KHH * 4 + 2 * PCHB);
        cudaFuncSetAttribute(lstm_main, cudaFuncAttributeMaxDynamicSharedMemorySize,
                             SM_MAIN);
        attr_done = true;
    }

    prep_hin<<<(NN * FD + 255) / 256, 256>>>(x, tids, emb);
    prep_w<<<(2 * 4 * 10 * 160 * 16 + 255) / 256, 256>>>(Wih, Whh, bih, bhh, Wl, Wr);
    prep_PQ<<<(NN + PTM - 1) / PTM, PNT, PTM * KHH * 4 + 2 * PCHB>>>(bl);
    lstm_main<<<(NN + TM - 1) / TM, NT, SM_MAIN>>>(eidx, out);
}

// round 13
// speedup vs baseline: 1.5894x; 1.0631x over previous
#include <cuda_runtime.h>
#include <cuda_bf16.h>
#include <cstdint>

#define NN   50000
#define DEG  16
#define FD   160
#define HD   160
#define GD   640
#define OC   128
#define KHH  160

// prep (fp32) config — proven machinery
#define PTM  64
#define PNT  512
#define PKC  16
#define PNCH (KHH/PKC)
#define PCHF (PKC*GD)
#define PCHB (PCHF*4)

// main MMA kernel config
#define TM   64
#define NT   256
#define HPLANE 21504               // bytes per h plane (64*168*2)
#define HBUFB  43008               // bytes per h buffer (2 planes)
#define SM_B   86016               // B double buffer: 2 x 38400 (48B padded rows)
#define BSTG   38400
#define SM_CST 162816              // 40*256*4
#define SM_SRC 203776              // 2*64 ints
#define SM_MAIN 204288

typedef unsigned long long ull;

// ---------------- device scratch ----------------
__device__ float g_hin[NN * FD];
__device__ float g_WihP[KHH * HD * 4];   // [k][m][4]
__device__ float g_bias[GD];             // [m][4]
__device__ float g_WlP[KHH * OC];
__device__ float g_WrP[KHH * OC];
__device__ float g_P[NN * GD];           // [node][4m+g], biases folded
__device__ float g_Q[NN * OC];
// Whh bf16 split: [pl 2][q 4][kc 10][n 160][16]  (unpadded in gmem)
__device__ __align__(16) __nv_bfloat16 g_Wb[2 * 4 * 10 * 160 * 16];

// ---------------- helpers ----------------
__device__ __forceinline__ ull pack2(float lo, float hi) {
    ull v; asm("mov.b64 %0, {%1, %2};" : "=l"(v) : "f"(lo), "f"(hi)); return v;
}
__device__ __forceinline__ void unpack2(ull v, float& lo, float& hi) {
    asm("mov.b64 {%0, %1}, %2;" : "=f"(lo), "=f"(hi) : "l"(v));
}
__device__ __forceinline__ void fma2(ull& d, ull a, ull b) {
    asm("fma.rn.f32x2 %0, %1, %2, %0;" : "+l"(d) : "l"(a), "l"(b));
}
__device__ __forceinline__ void ldsv2(uint32_t a, ull& x, ull& y) {
    asm("ld.shared.v2.u64 {%0,%1}, [%2];" : "=l"(x), "=l"(y) : "r"(a));
}
__device__ __forceinline__ void ldsm4(uint32_t* r, uint32_t a) {
    asm volatile("ldmatrix.sync.aligned.m8n8.x4.shared.b16 {%0,%1,%2,%3}, [%4];"
                 : "=r"(r[0]), "=r"(r[1]), "=r"(r[2]), "=r"(r[3]) : "r"(a));
}
__device__ __forceinline__ void ldsm2(uint32_t* r, uint32_t a) {
    asm volatile("ldmatrix.sync.aligned.m8n8.x2.shared.b16 {%0,%1}, [%2];"
                 : "=r"(r[0]), "=r"(r[1]) : "r"(a));
}
__device__ __forceinline__ void cp16(uint32_t s, const void* g) {
    asm volatile("cp.async.ca.shared.global [%0], [%1], 16;" :: "r"(s), "l"(g));
}
__device__ __forceinline__ void cpcommit() { asm volatile("cp.async.commit_group;"); }
template<int N> __device__ __forceinline__ void cpwait() {
    asm volatile("cp.async.wait_group %0;" :: "n"(N));
}
__device__ __forceinline__ float sigm(float x) { return __fdividef(1.f, 1.f + __expf(-x)); }
__device__ __forceinline__ float tanhfast(float x) {
    return __fdividef(2.f, 1.f + __expf(-2.f * x)) - 1.f;
}
__device__ __forceinline__ void mma_bf16(float* d, const uint32_t* a, uint32_t b0, uint32_t b1) {
    asm volatile("mma.sync.aligned.m16n8k16.row.col.f32.bf16.bf16.f32 "
                 "{%0,%1,%2,%3}, {%4,%5,%6,%7}, {%8,%9}, {%0,%1,%2,%3};"
                 : "+f"(d[0]), "+f"(d[1]), "+f"(d[2]), "+f"(d[3])
                 : "r"(a[0]), "r"(a[1]), "r"(a[2]), "r"(a[3]), "r"(b0), "r"(b1));
}

// ---------------- prep kernels ----------------
__global__ void prep_hin(const float* __restrict__ x, const int* __restrict__ tids,
                         const float* __restrict__ emb) {
    int i = blockIdx.x * blockDim.x + threadIdx.x;
    if (i >= NN * FD) return;
    int n = i / FD, c = i % FD;
    g_hin[i] = (c < 128) ? x[n * 128 + c] : emb[tids[n] * 32 + (c - 128)];
}

// prep_w also builds the bf16 hi/lo split of Whh
__global__ void prep_w(const float* __restrict__ Wih, const float* __restrict__ Whh,
                       const float* __restrict__ bih, const float* __restrict__ bhh,
                       const float* __restrict__ Wl,  const float* __restrict__ Wr) {
    int i = blockIdx.x * blockDim.x + threadIdx.x;
    if (i < KHH * HD * 4) {
        int g = i & 3, m = (i >> 2) % HD, k = (i >> 2) / HD;
        g_WihP[i] = Wih[(g * HD + m) * FD + k];
    }
    if (i < GD) {
        int m = i >> 2, g = i & 3;
        g_bias[i] = bih[g * HD + m] + bhh[g * HD + m];
    }
    if (i < KHH * OC) {
        int k = i / OC, j = i % OC;
        g_WlP[i] = Wl[j * FD + k];
        g_WrP[i] = Wr[j * FD + k];
    }
    if (i < 2 * 4 * 10 * 160 * 16) {
        int kk = i & 15;
        int n  = (i >> 4) % 160;
        int kc = (i / 2560) % 10;
        int q  = (i / 25600) % 4;
        int pl = i / 102400;
        int k = kc * 16 + kk;
        int gcl = q * 160 + n;
        int m = gcl >> 2, g = gcl & 3;
        float w = Whh[(g * HD + m) * HD + k];
        __nv_bfloat16 hb = __float2bfloat16(w);
        g_Wb[i] = pl ? __float2bfloat16(w - __bfloat162float(hb)) : hb;
    }
}

// ---- prep_PQ: fp32 K=160 GEMM (proven) ----
__device__ __forceinline__ void pstage(const float* gsrc, uint32_t sdst, int tid) {
#pragma unroll
    for (int u = 0; u < 5; u++)
        cp16(sdst + (uint32_t)(tid * 16 + u * 8192), gsrc + tid * 4 + u * 2048);
    cpcommit();
}
__device__ __forceinline__ void pgemm(const float* __restrict__ gW, uint32_t wsbase,
                                      const float* __restrict__ hrow, int tid, int c,
                                      ull accIF[4][5], ull accGO[4][5]) {
    pstage(gW, wsbase, tid);
    pstage(gW + PCHF, wsbase + PCHB, tid);
    for (int ch = 0; ch < PNCH; ch++) {
        if (ch == PNCH - 1) cpwait<0>(); else cpwait<1>();
        __syncthreads();
        const uint32_t wb0 = wsbase + (uint32_t)(ch & 1) * PCHB;
#pragma unroll
        for (int kq = 0; kq < 4; kq++) {
            float4 a4[4];
#pragma unroll
            for (int i = 0; i < 4; i++)
                a4[i] = *(const float4*)&hrow[i * KHH + ch * PKC + kq * 4];
#pragma unroll
            for (int k2 = 0; k2 < 4; k2++) {
                ull a2[4];
#pragma unroll
                for (int i = 0; i < 4; i++) {
                    float a = (k2 == 0) ? a4[i].x : (k2 == 1) ? a4[i].y
                             : (k2 == 2) ? a4[i].z : a4[i].w;
                    a2[i] = pack2(a, a);
                }
                const uint32_t wb = wb0 + (uint32_t)((kq * 4 + k2) * 2560 + c * 16);
#pragma unroll
                for (int n = 0; n < 5; n++) {
                    ull wif, wgo;
                    ldsv2(wb + (uint32_t)(n * 512), wif, wgo);
#pragma unroll
                    for (int i = 0; i < 4; i++) {
                        fma2(accIF[i][n], a2[i], wif);
                        fma2(accGO[i][n], a2[i], wgo);
                    }
                }
            }
        }
        __syncthreads();
        if (ch < PNCH - 2) pstage(gW + (ch + 2) * PCHF, wsbase + (uint32_t)(ch & 1) * PCHB, tid);
    }
}

__global__ void __launch_bounds__(PNT, 1)
prep_PQ(const float* __restrict__ bl) {
    extern __shared__ float sm[];
    float* hs = sm;
    const uint32_t sbase = (uint32_t)__cvta_generic_to_shared(sm);
    const uint32_t wsbase = sbase + PTM * KHH * 4;
    const int tid = threadIdx.x, c = tid & 31, warp = tid >> 5;
    const int nodeBase = blockIdx.x * PTM;
    float* hrow = hs + warp * 4 * KHH;

#pragma unroll
    for (int u = 0; u < 5; u++) {
        int idx4 = tid + u * PNT;
        int r = idx4 / 40, col4 = idx4 % 40;
        int node = nodeBase + r; if (node >= NN) node = NN - 1;
        ((float4*)hs)[idx4] = ((const float4*)g_hin)[node * 40 + col4];
    }
    __syncthreads();

    ull accIF[4][5], accGO[4][5];
#pragma unroll
    for (int n = 0; n < 5; n++) {
        float4 b = ((const float4*)g_bias)[n * 32 + c];
#pragma unroll
        for (int i = 0; i < 4; i++) {
            accIF[i][n] = pack2(b.x, b.y);
            accGO[i][n] = pack2(b.z, b.w);
        }
    }
    pgemm(g_WihP, wsbase, hrow, tid, c, accIF, accGO);

#pragma unroll
    for (int i = 0; i < 4; i++) {
        int node = nodeBase + warp * 4 + i;
        if (node < NN) {
#pragma unroll
            for (int n = 0; n < 5; n++) {
                float4 o;
                unpack2(accIF[i][n], o.x, o.y);
                unpack2(accGO[i][n], o.z, o.w);
                ((float4*)g_P)[node * 160 + n * 32 + c] = o;
            }
        }
    }

    __syncthreads();
    float* Wfs = hs + PTM * KHH;
    for (int u = tid; u < KHH * OC / 4; u += PNT)
        ((float4*)Wfs)[u] = ((const float4*)g_WrP)[u];
    __syncthreads();

    float4 q[4];
    float4 blv = ((const float4*)bl)[c];
#pragma unroll
    for (int i = 0; i < 4; i++) q[i] = blv;
    for (int k = 0; k < KHH; k++) {
        float4 w = ((const float4*)Wfs)[k * 32 + c];
#pragma unroll
        for (int i = 0; i < 4; i++) {
            float a = hrow[i * KHH + k];
            q[i].x = fmaf(a, w.x, q[i].x);
            q[i].y = fmaf(a, w.y, q[i].y);
            q[i].z = fmaf(a, w.z, q[i].z);
            q[i].w = fmaf(a, w.w, q[i].w);
        }
    }
#pragma unroll
    for (int i = 0; i < 4; i++) {
        int node = nodeBase + warp * 4 + i;
        if (node < NN) ((float4*)g_Q)[node * 32 + c] = q[i];
    }
}

// ---------------- main MMA recurrence kernel ----------------
// stage = 25600B data (5 kc x 160 n x 16 k bf16) scattered into 48B-padded rows
__device__ __forceinline__ void stageB38(uint32_t sdst, const __nv_bfloat16* g, int tid) {
#pragma unroll
    for (int u = 0; u < 6; u++) {
        int idx = tid + u * 256;                 // 0..1535
        int row = idx >> 1, ch = idx & 1;
        cp16(sdst + (uint32_t)(row * 48 + ch * 16), (const char*)g + (size_t)idx * 16);
    }
    if (tid < 64) {
        int idx = 1536 + tid;
        int row = idx >> 1, ch = idx & 1;
        cp16(sdst + (uint32_t)(row * 48 + ch * 16), (const char*)g + (size_t)idx * 16);
    }
    cpcommit();
}

// B-hi pass: load A-hi into cache (kept for the following B-lo pass), A-lo
// transient, B loaded ONCE per kcl, 20 HMMA/kcl.
__device__ __forceinline__ void mma5_hi(uint32_t aHi, uint32_t aLo,
                                        uint32_t b4, uint32_t b2,
                                        uint32_t aC[5][2][4], float acc[2][5][4]) {
#pragma unroll
    for (int kcl = 0; kcl < 5; kcl++) {
        ldsm4(aC[kcl][0], aHi + (uint32_t)(kcl * 32));
        ldsm4(aC[kcl][1], aHi + (uint32_t)(16 * 336 + kcl * 32));
        uint32_t al0[4], al1[4];
        ldsm4(al0, aLo + (uint32_t)(kcl * 32));
        ldsm4(al1, aLo + (uint32_t)(16 * 336 + kcl * 32));
        uint32_t b01[4], b23[4], b4r[2];
        ldsm4(b01, b4 + (uint32_t)(kcl * 7680));
        ldsm4(b23, b4 + (uint32_t)(kcl * 7680 + 768));
        ldsm2(b4r, b2 + (uint32_t)(kcl * 7680));
        mma_bf16(acc[0][0], aC[kcl][0], b01[0], b01[1]);
        mma_bf16(acc[1][0], aC[kcl][1], b01[0], b01[1]);
        mma_bf16(acc[0][1], aC[kcl][0], b01[2], b01[3]);
        mma_bf16(acc[1][1], aC[kcl][1], b01[2], b01[3]);
        mma_bf16(acc[0][2], aC[kcl][0], b23[0], b23[1]);
        mma_bf16(acc[1][2], aC[kcl][1], b23[0], b23[1]);
        mma_bf16(acc[0][3], aC[kcl][0], b23[2], b23[3]);
        mma_bf16(acc[1][3], aC[kcl][1], b23[2], b23[3]);
        mma_bf16(acc[0][4], aC[kcl][0], b4r[0], b4r[1]);
        mma_bf16(acc[1][4], aC[kcl][1], b4r[0], b4r[1]);
        mma_bf16(acc[0][0], al0, b01[0], b01[1]);
        mma_bf16(acc[1][0], al1, b01[0], b01[1]);
        mma_bf16(acc[0][1], al0, b01[2], b01[3]);
        mma_bf16(acc[1][1], al1, b01[2], b01[3]);
        mma_bf16(acc[0][2], al0, b23[0], b23[1]);
        mma_bf16(acc[1][2], al1, b23[0], b23[1]);
        mma_bf16(acc[0][3], al0, b23[2], b23[3]);
        mma_bf16(acc[1][3], al1, b23[2], b23[3]);
        mma_bf16(acc[0][4], al0, b4r[0], b4r[1]);
        mma_bf16(acc[1][4], al1, b4r[0], b4r[1]);
    }
}

// B-lo pass: A-hi comes from the register cache — ZERO A loads.
__device__ __forceinline__ void mma5_lo(const uint32_t aC[5][2][4],
                                        uint32_t b4, uint32_t b2, float acc[2][5][4]) {
#pragma unroll
    for (int kcl = 0; kcl < 5; kcl++) {
        uint32_t b01[4], b23[4], b4r[2];
        ldsm4(b01, b4 + (uint32_t)(kcl * 7680));
        ldsm4(b23, b4 + (uint32_t)(kcl * 7680 + 768));
        ldsm2(b4r, b2 + (uint32_t)(kcl * 7680));
        mma_bf16(acc[0][0], aC[kcl][0], b01[0], b01[1]);
        mma_bf16(acc[1][0], aC[kcl][1], b01[0], b01[1]);
        mma_bf16(acc[0][1], aC[kcl][0], b01[2], b01[3]);
        mma_bf16(acc[1][1], aC[kcl][1], b01[2], b01[3]);
        mma_bf16(acc[0][2], aC[kcl][0], b23[0], b23[1]);
        mma_bf16(acc[1][2], aC[kcl][1], b23[0], b23[1]);
        mma_bf16(acc[0][3], aC[kcl][0], b23[2], b23[3]);
        mma_bf16(acc[1][3], aC[kcl][1], b23[2], b23[3]);
        mma_bf16(acc[0][4], aC[kcl][0], b4r[0], b4r[1]);
        mma_bf16(acc[1][4], aC[kcl][1], b4r[0], b4r[1]);
    }
}

// stage r (0..15) within a step: q = r>>2, ph = r&3.
// ph0: B-hi half0 (dual A, cache A-hi)   ph1: B-lo half0 (cached A-hi)
// ph2: B-hi half1 (dual A, cache A-hi)   ph3: B-lo half1 (cached A-hi) + pointwise
__device__ __forceinline__ const __nv_bfloat16* bsrc(int r) {
    int q = r >> 2, ph = r & 3;
    return g_Wb + ((ph & 1) ? 102400 : 0) + q * 25600 + (ph >> 1) * 12800;
}

__global__ void __launch_bounds__(NT)
lstm_main(const int* __restrict__ esrc, float* __restrict__ out) {
    extern __shared__ char smraw[];
    __nv_bfloat16* hB = (__nv_bfloat16*)smraw;       // [2buf][2pl][64][168]
    float* cst = (float*)(smraw + SM_CST);
    int*   srcS = (int*)(smraw + SM_SRC);            // [2][64]
    const uint32_t sbase = (uint32_t)__cvta_generic_to_shared(smraw);

    const int tid = threadIdx.x, lane = tid & 31, warp = tid >> 5;
    const int q2 = lane & 3, r8 = lane >> 2;
    const int mg = warp & 1, ng = warp >> 1;
    const int lrow = lane & 15, lkoff = (lane >> 4) * 16;
    const int nodeBase = blockIdx.x * TM;

    for (int i = tid; i < 21504; i += NT) hB[i] = __float2bfloat16(0.f);
#pragma unroll
    for (int j = 0; j < 40; j++) cst[j * NT + tid] = 0.f;
    if (tid < TM) {
        int node = nodeBase + tid; if (node >= NN) node = NN - 1;
        srcS[tid] = esrc[node * DEG];
    }
    stageB38(sbase + SM_B, bsrc(0), tid);
    stageB38(sbase + SM_B + BSTG, bsrc(1), tid);

    float acc[2][5][4];
    uint32_t aC[5][2][4];

    for (int s = 0; s < 256; s++) {
        const int t = s >> 4, r = s & 15, q = r >> 2, ph = r & 3;
        if (s == 255) cpwait<0>(); else cpwait<1>();
        __syncthreads();
        const uint32_t hRd = sbase + (uint32_t)(t & 1) * HBUFB;
        const uint32_t bB = sbase + SM_B + (uint32_t)(s & 1) * BSTG;
        const int kcb = (ph >> 1) * 5;

        if (ph == 0) {
            // acc init from P (biases folded)
            const int gb = q * 160 + ng * 40 + q2 * 2;
            const int* sp = srcS + (t & 1) * 64;
#pragma unroll
            for (int mt = 0; mt < 2; mt++) {
                int rr = mg * 32 + mt * 16 + r8;
                const float* p0 = g_P + (size_t)sp[rr] * 640 + gb;
                const float* p8 = g_P + (size_t)sp[rr + 8] * 640 + gb;
#pragma unroll
                for (int nt = 0; nt < 5; nt++) {
                    float2 v0 = *(const float2*)(p0 + nt * 8);
                    float2 v8 = *(const float2*)(p8 + nt * 8);
                    acc[mt][nt][0] = v0.x; acc[mt][nt][1] = v0.y;
                    acc[mt][nt][2] = v8.x; acc[mt][nt][3] = v8.y;
                }
            }
            if (q == 0 && t < DEG - 1 && tid < TM) {
                int node = nodeBase + tid; if (node >= NN) node = NN - 1;
                srcS[((t + 1) & 1) * 64 + tid] = esrc[node * DEG + t + 1];
            }
        }

        const uint32_t aB0 = hRd + (uint32_t)((mg * 32 + lrow) * 336 + kcb * 32 + lkoff);
        const uint32_t bB4 = bB + (uint32_t)((ng * 40 + ((lane >> 4) & 1) * 8
                                              + (lane & 7)) * 48 + ((lane >> 3) & 1) * 16);
        const uint32_t bB2 = bB + (uint32_t)((ng * 40 + 32 + (lane & 7)) * 48
                                              + ((lane >> 3) & 1) * 16);
        if ((ph & 1) == 0) {
            mma5_hi(aB0, aB0 + HPLANE, bB4, bB2, aC, acc);   // (A-hi + A-lo) x B-hi
        } else {
            mma5_lo(aC, bB4, bB2, acc);                       // cached A-hi x B-lo
        }

        if (ph == 3) {
            // pointwise; lane pair (i,f)|(g,o) exchange via shfl_xor(1)
            __nv_bfloat16* hWr = hB + ((t + 1) & 1) * 21504;
#pragma unroll
            for (int mt = 0; mt < 2; mt++) {
                int rw = mg * 32 + mt * 16 + r8 + ((q2 & 1) ? 8 : 0);
#pragma unroll
                for (int nt = 0; nt < 5; nt++) {
                    float ox = __shfl_xor_sync(0xffffffff, acc[mt][nt][0], 1);
                    float oy = __shfl_xor_sync(0xffffffff, acc[mt][nt][1], 1);
                    float oz = __shfl_xor_sync(0xffffffff, acc[mt][nt][2], 1);
                    float ow = __shfl_xor_sync(0xffffffff, acc[mt][nt][3], 1);
                    float gi, gf, gg, go;
                    if (!(q2 & 1)) { gi = acc[mt][nt][0]; gf = acc[mt][nt][1]; gg = ox; go = oy; }
                    else           { gi = oz; gf = ow; gg = acc[mt][nt][2]; go = acc[mt][nt][3]; }
                    int m = q * 40 + ng * 10 + nt * 2 + (q2 >> 1);
                    int slot = q * 10 + mt * 5 + nt;
                    float cv = sigm(gf) * cst[slot * NT + tid] + sigm(gi) * tanhfast(gg);
                    cst[slot * NT + tid] = cv;
                    float hv = sigm(go) * tanhfast(cv);
                    __nv_bfloat16 hh = __float2bfloat16(hv);
                    hWr[rw * 168 + m] = hh;
                    hWr[10752 + rw * 168 + m] = __float2bfloat16(hv - __bfloat162float(hh));
                }
            }
        }
        __syncthreads();
        if (s + 2 < 256) {
            stageB38(sbase + SM_B + (uint32_t)(s & 1) * BSTG, bsrc((s + 2) & 15), tid);
        }
    }

    // ---- final layer: out = relu(Q[node] + h @ Wl^T); h last in buf0
    __syncthreads();
    const __nv_bfloat16* hf = hB;
    const __nv_bfloat16* hl = hB + 10752;
#pragma unroll
    for (int rr = 0; rr < 8; rr++) {
        int row = warp * 8 + rr;
        int node = nodeBase + row;
        int nc = node < NN ? node : NN - 1;
        float4 qv = ((const float4*)g_Q)[nc * 32 + lane];
        for (int k = 0; k < KHH; k++) {
            float a = __bfloat162float(hf[row * 168 + k]) +
                      __bfloat162float(hl[row * 168 + k]);
            float4 w = *(const float4*)&g_WlP[k * OC + lane * 4];
            qv.x = fmaf(a, w.x, qv.x);
            qv.y = fmaf(a, w.y, qv.y);
            qv.z = fmaf(a, w.z, qv.z);
            qv.w = fmaf(a, w.w, qv.w);
        }
        if (node < NN) {
            float4 o;
            o.x = fmaxf(qv.x, 0.f); o.y = fmaxf(qv.y, 0.f);
            o.z = fmaxf(qv.z, 0.f); o.w = fmaxf(qv.w, 0.f);
            ((float4*)out)[node * 32 + lane] = o;
        }
    }
}

// ---------------- launch ----------------
extern "C" void kernel_launch(void* const* d_in, const int* in_sizes, int n_in,
                              void* d_out, int out_size) {
    const float* x    = (const float*)d_in[0];
    const int*   tids = (const int*)  d_in[1];
    const int*   eidx = (const int*)  d_in[2];
    const float* emb  = (const float*)d_in[3];
    const float* Wih  = (const float*)d_in[4];
    const float* Whh  = (const float*)d_in[5];
    const float* bih  = (const float*)d_in[6];
    const float* bhh  = (const float*)d_in[7];
    const float* Wl   = (const float*)d_in[8];
    const float* bl   = (const float*)d_in[9];
    const float* Wr   = (const float*)d_in[10];
    float* out = (float*)d_out;

    static bool attr_done = false;
    if (!attr_done) {
        cudaFuncSetAttribute(prep_PQ, cudaFuncAttributeMaxDynamicSharedMemorySize,
                             PTM * KHH * 4 + 2 * PCHB);
        cudaFuncSetAttribute(lstm_main, cudaFuncAttributeMaxDynamicSharedMemorySize,
                             SM_MAIN);
        attr_done = true;
    }

    prep_hin<<<(NN * FD + 255) / 256, 256>>>(x, tids, emb);
    prep_w<<<(2 * 4 * 10 * 160 * 16 + 255) / 256, 256>>>(Wih, Whh, bih, bhh, Wl, Wr);
    prep_PQ<<<(NN + PTM - 1) / PTM, PNT, PTM * KHH * 4 + 2 * PCHB>>>(bl);
    lstm_main<<<(NN + TM - 1) / TM, NT, SM_MAIN>>>(eidx, out);
}

// round 14
// speedup vs baseline: 1.5994x; 1.0063x over previous
#include <cuda_runtime.h>
#include <cuda_bf16.h>
#include <cstdint>

#define NN   50000
#define DEG  16
#define FD   160
#define HD   160
#define GD   640
#define OC   128
#define KHH  160

// prep (fp32) config — proven machinery
#define PTM  64
#define PNT  512
#define PKC  16
#define PNCH (KHH/PKC)
#define PCHF (PKC*GD)
#define PCHB (PCHF*4)

// main MMA kernel config
#define TM   64
#define MNT  512                   // 16 warps = 4 M-groups x 4 N-groups
#define HPLANE 21504               // bytes per h plane (64*168*2)
#define HBUFB  43008               // bytes per h buffer (2 planes)
#define SM_B   86016               // B double buffer: 2 x 38400 (48B padded rows)
#define BSTG   38400
#define SM_CST 162816              // 20*512*4 = 40960
#define SM_SRC 203776              // 2*64 ints
#define SM_MAIN 204288

typedef unsigned long long ull;

// ---------------- device scratch ----------------
__device__ float g_hin[NN * FD];
__device__ float g_WihP[KHH * HD * 4];   // [k][m][4]
__device__ float g_bias[GD];             // [m][4]
__device__ float g_WlP[KHH * OC];
__device__ float g_WrP[KHH * OC];
__device__ float g_P[NN * GD];           // [node][4m+g], biases folded
__device__ float g_Q[NN * OC];
// Whh bf16 split: [pl 2][q 4][kc 10][n 160][16]  (unpadded in gmem)
__device__ __align__(16) __nv_bfloat16 g_Wb[2 * 4 * 10 * 160 * 16];

// ---------------- helpers ----------------
__device__ __forceinline__ ull pack2(float lo, float hi) {
    ull v; asm("mov.b64 %0, {%1, %2};" : "=l"(v) : "f"(lo), "f"(hi)); return v;
}
__device__ __forceinline__ void unpack2(ull v, float& lo, float& hi) {
    asm("mov.b64 {%0, %1}, %2;" : "=f"(lo), "=f"(hi) : "l"(v));
}
__device__ __forceinline__ void fma2(ull& d, ull a, ull b) {
    asm("fma.rn.f32x2 %0, %1, %2, %0;" : "+l"(d) : "l"(a), "l"(b));
}
__device__ __forceinline__ void ldsv2(uint32_t a, ull& x, ull& y) {
    asm("ld.shared.v2.u64 {%0,%1}, [%2];" : "=l"(x), "=l"(y) : "r"(a));
}
__device__ __forceinline__ void ldsm4(uint32_t* r, uint32_t a) {
    asm volatile("ldmatrix.sync.aligned.m8n8.x4.shared.b16 {%0,%1,%2,%3}, [%4];"
                 : "=r"(r[0]), "=r"(r[1]), "=r"(r[2]), "=r"(r[3]) : "r"(a));
}
__device__ __forceinline__ void ldsm2(uint32_t* r, uint32_t a) {
    asm volatile("ldmatrix.sync.aligned.m8n8.x2.shared.b16 {%0,%1}, [%2];"
                 : "=r"(r[0]), "=r"(r[1]) : "r"(a));
}
__device__ __forceinline__ void cp16(uint32_t s, const void* g) {
    asm volatile("cp.async.ca.shared.global [%0], [%1], 16;" :: "r"(s), "l"(g));
}
__device__ __forceinline__ void cpcommit() { asm volatile("cp.async.commit_group;"); }
template<int N> __device__ __forceinline__ void cpwait() {
    asm volatile("cp.async.wait_group %0;" :: "n"(N));
}
__device__ __forceinline__ float sigm(float x) { return __fdividef(1.f, 1.f + __expf(-x)); }
__device__ __forceinline__ float tanhfast(float x) {
    return __fdividef(2.f, 1.f + __expf(-2.f * x)) - 1.f;
}
__device__ __forceinline__ void mma_bf16(float* d, const uint32_t* a, uint32_t b0, uint32_t b1) {
    asm volatile("mma.sync.aligned.m16n8k16.row.col.f32.bf16.bf16.f32 "
                 "{%0,%1,%2,%3}, {%4,%5,%6,%7}, {%8,%9}, {%0,%1,%2,%3};"
                 : "+f"(d[0]), "+f"(d[1]), "+f"(d[2]), "+f"(d[3])
                 : "r"(a[0]), "r"(a[1]), "r"(a[2]), "r"(a[3]), "r"(b0), "r"(b1));
}

// ---------------- prep kernels ----------------
__global__ void prep_hin(const float* __restrict__ x, const int* __restrict__ tids,
                         const float* __restrict__ emb) {
    int i = blockIdx.x * blockDim.x + threadIdx.x;
    if (i >= NN * FD) return;
    int n = i / FD, c = i % FD;
    g_hin[i] = (c < 128) ? x[n * 128 + c] : emb[tids[n] * 32 + (c - 128)];
}

// prep_w also builds the bf16 hi/lo split of Whh
__global__ void prep_w(const float* __restrict__ Wih, const float* __restrict__ Whh,
                       const float* __restrict__ bih, const float* __restrict__ bhh,
                       const float* __restrict__ Wl,  const float* __restrict__ Wr) {
    int i = blockIdx.x * blockDim.x + threadIdx.x;
    if (i < KHH * HD * 4) {
        int g = i & 3, m = (i >> 2) % HD, k = (i >> 2) / HD;
        g_WihP[i] = Wih[(g * HD + m) * FD + k];
    }
    if (i < GD) {
        int m = i >> 2, g = i & 3;
        g_bias[i] = bih[g * HD + m] + bhh[g * HD + m];
    }
    if (i < KHH * OC) {
        int k = i / OC, j = i % OC;
        g_WlP[i] = Wl[j * FD + k];
        g_WrP[i] = Wr[j * FD + k];
    }
    if (i < 2 * 4 * 10 * 160 * 16) {
        int kk = i & 15;
        int n  = (i >> 4) % 160;
        int kc = (i / 2560) % 10;
        int q  = (i / 25600) % 4;
        int pl = i / 102400;
        int k = kc * 16 + kk;
        int gcl = q * 160 + n;
        int m = gcl >> 2, g = gcl & 3;
        float w = Whh[(g * HD + m) * HD + k];
        __nv_bfloat16 hb = __float2bfloat16(w);
        g_Wb[i] = pl ? __float2bfloat16(w - __bfloat162float(hb)) : hb;
    }
}

// ---- prep_PQ: fp32 K=160 GEMM (proven) ----
__device__ __forceinline__ void pstage(const float* gsrc, uint32_t sdst, int tid) {
#pragma unroll
    for (int u = 0; u < 5; u++)
        cp16(sdst + (uint32_t)(tid * 16 + u * 8192), gsrc + tid * 4 + u * 2048);
    cpcommit();
}
__device__ __forceinline__ void pgemm(const float* __restrict__ gW, uint32_t wsbase,
                                      const float* __restrict__ hrow, int tid, int c,
                                      ull accIF[4][5], ull accGO[4][5]) {
    pstage(gW, wsbase, tid);
    pstage(gW + PCHF, wsbase + PCHB, tid);
    for (int ch = 0; ch < PNCH; ch++) {
        if (ch == PNCH - 1) cpwait<0>(); else cpwait<1>();
        __syncthreads();
        const uint32_t wb0 = wsbase + (uint32_t)(ch & 1) * PCHB;
#pragma unroll
        for (int kq = 0; kq < 4; kq++) {
            float4 a4[4];
#pragma unroll
            for (int i = 0; i < 4; i++)
                a4[i] = *(const float4*)&hrow[i * KHH + ch * PKC + kq * 4];
#pragma unroll
            for (int k2 = 0; k2 < 4; k2++) {
                ull a2[4];
#pragma unroll
                for (int i = 0; i < 4; i++) {
                    float a = (k2 == 0) ? a4[i].x : (k2 == 1) ? a4[i].y
                             : (k2 == 2) ? a4[i].z : a4[i].w;
                    a2[i] = pack2(a, a);
                }
                const uint32_t wb = wb0 + (uint32_t)((kq * 4 + k2) * 2560 + c * 16);
#pragma unroll
                for (int n = 0; n < 5; n++) {
                    ull wif, wgo;
                    ldsv2(wb + (uint32_t)(n * 512), wif, wgo);
#pragma unroll
                    for (int i = 0; i < 4; i++) {
                        fma2(accIF[i][n], a2[i], wif);
                        fma2(accGO[i][n], a2[i], wgo);
                    }
                }
            }
        }
        __syncthreads();
        if (ch < PNCH - 2) pstage(gW + (ch + 2) * PCHF, wsbase + (uint32_t)(ch & 1) * PCHB, tid);
    }
}

__global__ void __launch_bounds__(PNT, 1)
prep_PQ(const float* __restrict__ bl) {
    extern __shared__ float sm[];
    float* hs = sm;
    const uint32_t sbase = (uint32_t)__cvta_generic_to_shared(sm);
    const uint32_t wsbase = sbase + PTM * KHH * 4;
    const int tid = threadIdx.x, c = tid & 31, warp = tid >> 5;
    const int nodeBase = blockIdx.x * PTM;
    float* hrow = hs + warp * 4 * KHH;

#pragma unroll
    for (int u = 0; u < 5; u++) {
        int idx4 = tid + u * PNT;
        int r = idx4 / 40, col4 = idx4 % 40;
        int node = nodeBase + r; if (node >= NN) node = NN - 1;
        ((float4*)hs)[idx4] = ((const float4*)g_hin)[node * 40 + col4];
    }
    __syncthreads();

    ull accIF[4][5], accGO[4][5];
#pragma unroll
    for (int n = 0; n < 5; n++) {
        float4 b = ((const float4*)g_bias)[n * 32 + c];
#pragma unroll
        for (int i = 0; i < 4; i++) {
            accIF[i][n] = pack2(b.x, b.y);
            accGO[i][n] = pack2(b.z, b.w);
        }
    }
    pgemm(g_WihP, wsbase, hrow, tid, c, accIF, accGO);

#pragma unroll
    for (int i = 0; i < 4; i++) {
        int node = nodeBase + warp * 4 + i;
        if (node < NN) {
#pragma unroll
            for (int n = 0; n < 5; n++) {
                float4 o;
                unpack2(accIF[i][n], o.x, o.y);
                unpack2(accGO[i][n], o.z, o.w);
                ((float4*)g_P)[node * 160 + n * 32 + c] = o;
            }
        }
    }

    __syncthreads();
    float* Wfs = hs + PTM * KHH;
    for (int u = tid; u < KHH * OC / 4; u += PNT)
        ((float4*)Wfs)[u] = ((const float4*)g_WrP)[u];
    __syncthreads();

    float4 q[4];
    float4 blv = ((const float4*)bl)[c];
#pragma unroll
    for (int i = 0; i < 4; i++) q[i] = blv;
    for (int k = 0; k < KHH; k++) {
        float4 w = ((const float4*)Wfs)[k * 32 + c];
#pragma unroll
        for (int i = 0; i < 4; i++) {
            float a = hrow[i * KHH + k];
            q[i].x = fmaf(a, w.x, q[i].x);
            q[i].y = fmaf(a, w.y, q[i].y);
            q[i].z = fmaf(a, w.z, q[i].z);
            q[i].w = fmaf(a, w.w, q[i].w);
        }
    }
#pragma unroll
    for (int i = 0; i < 4; i++) {
        int node = nodeBase + warp * 4 + i;
        if (node < NN) ((float4*)g_Q)[node * 32 + c] = q[i];
    }
}

// ---------------- main MMA recurrence kernel ----------------
// stage = 25600B data (5 kc x 160 n x 16 k bf16) scattered into 48B-padded rows
__device__ __forceinline__ void stageB38(uint32_t sdst, const __nv_bfloat16* g, int tid) {
#pragma unroll
    for (int u = 0; u < 3; u++) {
        int idx = tid + u * MNT;                 // 0..1535
        int row = idx >> 1, ch = idx & 1;
        cp16(sdst + (uint32_t)(row * 48 + ch * 16), (const char*)g + (size_t)idx * 16);
    }
    if (tid < 64) {
        int idx = 1536 + tid;
        int row = idx >> 1, ch = idx & 1;
        cp16(sdst + (uint32_t)(row * 48 + ch * 16), (const char*)g + (size_t)idx * 16);
    }
    cpcommit();
}

// B-hi pass: load A-hi into cache (kept for the following B-lo pass), A-lo
// transient, B loaded ONCE per kcl, 10 HMMA/kcl (1 mtile).
__device__ __forceinline__ void mma5_hi(uint32_t aHi, uint32_t aLo,
                                        uint32_t b4, uint32_t b2,
                                        uint32_t aC[5][4], float acc[5][4]) {
#pragma unroll
    for (int kcl = 0; kcl < 5; kcl++) {
        ldsm4(aC[kcl], aHi + (uint32_t)(kcl * 32));
        uint32_t al[4];
        ldsm4(al, aLo + (uint32_t)(kcl * 32));
        uint32_t b01[4], b23[4], b4r[2];
        ldsm4(b01, b4 + (uint32_t)(kcl * 7680));
        ldsm4(b23, b4 + (uint32_t)(kcl * 7680 + 768));
        ldsm2(b4r, b2 + (uint32_t)(kcl * 7680));
        mma_bf16(acc[0], aC[kcl], b01[0], b01[1]);
        mma_bf16(acc[1], aC[kcl], b01[2], b01[3]);
        mma_bf16(acc[2], aC[kcl], b23[0], b23[1]);
        mma_bf16(acc[3], aC[kcl], b23[2], b23[3]);
        mma_bf16(acc[4], aC[kcl], b4r[0], b4r[1]);
        mma_bf16(acc[0], al, b01[0], b01[1]);
        mma_bf16(acc[1], al, b01[2], b01[3]);
        mma_bf16(acc[2], al, b23[0], b23[1]);
        mma_bf16(acc[3], al, b23[2], b23[3]);
        mma_bf16(acc[4], al, b4r[0], b4r[1]);
    }
}

// B-lo pass: A-hi comes from the register cache — ZERO A loads.
__device__ __forceinline__ void mma5_lo(const uint32_t aC[5][4],
                                        uint32_t b4, uint32_t b2, float acc[5][4]) {
#pragma unroll
    for (int kcl = 0; kcl < 5; kcl++) {
        uint32_t b01[4], b23[4], b4r[2];
        ldsm4(b01, b4 + (uint32_t)(kcl * 7680));
        ldsm4(b23, b4 + (uint32_t)(kcl * 7680 + 768));
        ldsm2(b4r, b2 + (uint32_t)(kcl * 7680));
        mma_bf16(acc[0], aC[kcl], b01[0], b01[1]);
        mma_bf16(acc[1], aC[kcl], b01[2], b01[3]);
        mma_bf16(acc[2], aC[kcl], b23[0], b23[1]);
        mma_bf16(acc[3], aC[kcl], b23[2], b23[3]);
        mma_bf16(acc[4], aC[kcl], b4r[0], b4r[1]);
    }
}

// stage r (0..15) within a step: q = r>>2, ph = r&3.
// ph0: B-hi half0 (dual A, cache A-hi)   ph1: B-lo half0 (cached A-hi)
// ph2: B-hi half1 (dual A, cache A-hi)   ph3: B-lo half1 (cached A-hi) + pointwise
__device__ __forceinline__ const __nv_bfloat16* bsrc(int r) {
    int q = r >> 2, ph = r & 3;
    return g_Wb + ((ph & 1) ? 102400 : 0) + q * 25600 + (ph >> 1) * 12800;
}

__global__ void __launch_bounds__(MNT)
lstm_main(const int* __restrict__ esrc, float* __restrict__ out) {
    extern __shared__ char smraw[];
    __nv_bfloat16* hB = (__nv_bfloat16*)smraw;       // [2buf][2pl][64][168]
    float* cst = (float*)(smraw + SM_CST);           // [20][512]
    int*   srcS = (int*)(smraw + SM_SRC);            // [2][64]
    const uint32_t sbase = (uint32_t)__cvta_generic_to_shared(smraw);

    const int tid = threadIdx.x, lane = tid & 31, warp = tid >> 5;
    const int q2 = lane & 3, r8 = lane >> 2;
    const int mg = warp & 3, ng = warp >> 2;         // 4 M-groups x 4 N-groups
    const int lrow = lane & 15, lkoff = (lane >> 4) * 16;
    const int nodeBase = blockIdx.x * TM;

    for (int i = tid; i < 21504; i += MNT) hB[i] = __float2bfloat16(0.f);
#pragma unroll
    for (int j = 0; j < 20; j++) cst[j * MNT + tid] = 0.f;
    if (tid < TM) {
        int node = nodeBase + tid; if (node >= NN) node = NN - 1;
        srcS[tid] = esrc[node * DEG];
    }
    stageB38(sbase + SM_B, bsrc(0), tid);
    stageB38(sbase + SM_B + BSTG, bsrc(1), tid);

    float acc[5][4];
    uint32_t aC[5][4];

    for (int s = 0; s < 256; s++) {
        const int t = s >> 4, r = s & 15, q = r >> 2, ph = r & 3;
        if (s == 255) cpwait<0>(); else cpwait<1>();
        __syncthreads();
        const uint32_t hRd = sbase + (uint32_t)(t & 1) * HBUFB;
        const uint32_t bB = sbase + SM_B + (uint32_t)(s & 1) * BSTG;
        const int kcb = (ph >> 1) * 5;

        if (ph == 0) {
            // acc init from P (biases folded)
            const int gb = q * 160 + ng * 40 + q2 * 2;
            const int* sp = srcS + (t & 1) * 64;
            int rr = mg * 16 + r8;
            const float* p0 = g_P + (size_t)sp[rr] * 640 + gb;
            const float* p8 = g_P + (size_t)sp[rr + 8] * 640 + gb;
#pragma unroll
            for (int nt = 0; nt < 5; nt++) {
                float2 v0 = *(const float2*)(p0 + nt * 8);
                float2 v8 = *(const float2*)(p8 + nt * 8);
                acc[nt][0] = v0.x; acc[nt][1] = v0.y;
                acc[nt][2] = v8.x; acc[nt][3] = v8.y;
            }
            if (q == 0 && t < DEG - 1 && tid < TM) {
                int node = nodeBase + tid; if (node >= NN) node = NN - 1;
                srcS[((t + 1) & 1) * 64 + tid] = esrc[node * DEG + t + 1];
            }
        }

        const uint32_t aB0 = hRd + (uint32_t)((mg * 16 + lrow) * 336 + kcb * 32 + lkoff);
        const uint32_t bB4 = bB + (uint32_t)((ng * 40 + ((lane >> 4) & 1) * 8
                                              + (lane & 7)) * 48 + ((lane >> 3) & 1) * 16);
        const uint32_t bB2 = bB + (uint32_t)((ng * 40 + 32 + (lane & 7)) * 48
                                              + ((lane >> 3) & 1) * 16);
        if ((ph & 1) == 0) {
            mma5_hi(aB0, aB0 + HPLANE, bB4, bB2, aC, acc);   // (A-hi + A-lo) x B-hi
        } else {
            mma5_lo(aC, bB4, bB2, acc);                       // cached A-hi x B-lo
        }

        if (ph == 3) {
            // pointwise; lane pair (i,f)|(g,o) exchange via shfl_xor(1)
            __nv_bfloat16* hWr = hB + ((t + 1) & 1) * 21504;
            int rw = mg * 16 + r8 + ((q2 & 1) ? 8 : 0);
#pragma unroll
            for (int nt = 0; nt < 5; nt++) {
                float ox = __shfl_xor_sync(0xffffffff, acc[nt][0], 1);
                float oy = __shfl_xor_sync(0xffffffff, acc[nt][1], 1);
                float oz = __shfl_xor_sync(0xffffffff, acc[nt][2], 1);
                float ow = __shfl_xor_sync(0xffffffff, acc[nt][3], 1);
                float gi, gf, gg, go;
                if (!(q2 & 1)) { gi = acc[nt][0]; gf = acc[nt][1]; gg = ox; go = oy; }
                else           { gi = oz; gf = ow; gg = acc[nt][2]; go = acc[nt][3]; }
                int m = q * 40 + ng * 10 + nt * 2 + (q2 >> 1);
                int slot = q * 5 + nt;
                float cv = sigm(gf) * cst[slot * MNT + tid] + sigm(gi) * tanhfast(gg);
                cst[slot * MNT + tid] = cv;
                float hv = sigm(go) * tanhfast(cv);
                __nv_bfloat16 hh = __float2bfloat16(hv);
                hWr[rw * 168 + m] = hh;
                hWr[10752 + rw * 168 + m] = __float2bfloat16(hv - __bfloat162float(hh));
            }
        }
        __syncthreads();
        if (s + 2 < 256) {
            stageB38(sbase + SM_B + (uint32_t)(s & 1) * BSTG, bsrc((s + 2) & 15), tid);
        }
    }

    // ---- final layer: out = relu(Q[node] + h @ Wl^T); h last in buf0
    __syncthreads();
    const __nv_bfloat16* hf = hB;
    const __nv_bfloat16* hl = hB + 10752;
#pragma unroll
    for (int rr = 0; rr < 4; rr++) {
        int row = warp * 4 + rr;
        int node = nodeBase + row;
        int nc = node < NN ? node : NN - 1;
        float4 qv = ((const float4*)g_Q)[nc * 32 + lane];
        for (int k = 0; k < KHH; k++) {
            float a = __bfloat162float(hf[row * 168 + k]) +
                      __bfloat162float(hl[row * 168 + k]);
            float4 w = *(const float4*)&g_WlP[k * OC + lane * 4];
            qv.x = fmaf(a, w.x, qv.x);
            qv.y = fmaf(a, w.y, qv.y);
            qv.z = fmaf(a, w.z, qv.z);
            qv.w = fmaf(a, w.w, qv.w);
        }
        if (node < NN) {
            float4 o;
            o.x = fmaxf(qv.x, 0.f); o.y = fmaxf(qv.y, 0.f);
            o.z = fmaxf(qv.z, 0.f); o.w = fmaxf(qv.w, 0.f);
            ((float4*)out)[node * 32 + lane] = o;
        }
    }
}

// ---------------- launch ----------------
extern "C" void kernel_launch(void* const* d_in, const int* in_sizes, int n_in,
                              void* d_out, int out_size) {
    const float* x    = (const float*)d_in[0];
    const int*   tids = (const int*)  d_in[1];
    const int*   eidx = (const int*)  d_in[2];
    const float* emb  = (const float*)d_in[3];
    const float* Wih  = (const float*)d_in[4];
    const float* Whh  = (const float*)d_in[5];
    const float* bih  = (const float*)d_in[6];
    const float* bhh  = (const float*)d_in[7];
    const float* Wl   = (const float*)d_in[8];
    const float* bl   = (const float*)d_in[9];
    const float* Wr   = (const float*)d_in[10];
    float* out = (float*)d_out;

    static bool attr_done = false;
    if (!attr_done) {
        cudaFuncSetAttribute(prep_PQ, cudaFuncAttributeMaxDynamicSharedMemorySize,
                             PTM * KHH * 4 + 2 * PCHB);
        cudaFuncSetAttribute(lstm_main, cudaFuncAttributeMaxDynamicSharedMemorySize,
                             SM_MAIN);
        attr_done = true;
    }

    prep_hin<<<(NN * FD + 255) / 256, 256>>>(x, tids, emb);
    prep_w<<<(2 * 4 * 10 * 160 * 16 + 255) / 256, 256>>>(Wih, Whh, bih, bhh, Wl, Wr);
    prep_PQ<<<(NN + PTM - 1) / PTM, PNT, PTM * KHH * 4 + 2 * PCHB>>>(bl);
    lstm_main<<<(NN + TM - 1) / TM, MNT, SM_MAIN>>>(eidx, out);
}